// round 1
// baseline (speedup 1.0000x reference)
#include <cuda_runtime.h>
#include <math.h>
#include <stdint.h>

// Problem constants
#define TT 512
#define NBATCH 64      // B*A
#define HID 512
#define DIN 512
#define G3 1536        // 3*HID
#define BBATCH 8
#define AAGENT 8
#define LLAYER 2

// ---------------------------------------------------------------------------
// Scratch (device globals; no allocations allowed)
// ---------------------------------------------------------------------------
__device__ float g_XW1[(size_t)TT * NBATCH * G3];   // 192 MB: XW_f, later XW_c
__device__ float g_XW2[(size_t)TT * NBATCH * G3];   // 192 MB: XW_b, later NXT
__device__ float g_ENCF[(size_t)TT * NBATCH * HID]; // 64 MB
__device__ float g_ENCB[(size_t)TT * NBATCH * HID]; // 64 MB (stored at original t index)
__device__ float g_ENC [(size_t)TT * NBATCH * HID]; // 64 MB
__device__ float g_hsm [NBATCH * HID];
__device__ float g_msg [NBATCH * HID];
__device__ float g_msgp[NBATCH * HID];
__device__ unsigned g_bar_count[8];
__device__ unsigned g_bar_gen[8];

// ---------------------------------------------------------------------------
// Software grid barrier (per-group). All CTAs of a group must be co-resident.
// ---------------------------------------------------------------------------
__device__ __forceinline__ void grid_barrier(int id, int ncta) {
    __threadfence();
    __syncthreads();
    if (threadIdx.x == 0) {
        volatile unsigned* genp = &g_bar_gen[id];
        unsigned g = *genp;
        __threadfence();
        unsigned old = atomicAdd(&g_bar_count[id], 1u);
        if (old == (unsigned)(ncta - 1)) {
            g_bar_count[id] = 0;
            __threadfence();
            *genp = g + 1u;
        } else {
            while (*genp == g) { }
        }
        __threadfence();
    }
    __syncthreads();
}

// ---------------------------------------------------------------------------
// SGEMM: C[M,Nc] = op(A) @ B (+ bias[col]) (+ rowAdd[m%64, col])
//   A row-major. If A2 != null: logical K=1024, k<512 from A (lda=512),
//   k>=512 from A2 (lda=512). If revT: A physical row = (511 - m/64)*64 + m%64.
//   B row-major [K, Nc]. 128x128 tile, BK=8, 256 threads, 8x8 microtile.
// ---------------------------------------------------------------------------
__global__ __launch_bounds__(256) void sgemm(
    const float* __restrict__ A, const float* __restrict__ A2,
    const float* __restrict__ Bm, const float* __restrict__ bias,
    const float* __restrict__ rowAdd, float* __restrict__ C,
    int M, int K, int Nc, int revT)
{
    __shared__ float As[8][128];
    __shared__ float Bs[8][128];

    const int tid  = threadIdx.x;
    const int row0 = blockIdx.y * 128;
    const int col0 = blockIdx.x * 128;

    const int la_r = tid >> 1;
    const int la_k = (tid & 1) * 4;
    const int lb_k = tid >> 5;
    const int lb_c = (tid & 31) * 4;

    const int warp = tid >> 5;
    const int lane = tid & 31;
    const int wr = warp & 3, wc = warp >> 2;      // 4x2 warps
    const int lr = lane >> 3, lc = lane & 7;      // 4x8 lanes
    const int tr = wr * 32 + lr * 8;
    const int tc = wc * 64 + lc * 8;

    float acc[8][8];
#pragma unroll
    for (int i = 0; i < 8; i++)
#pragma unroll
        for (int j = 0; j < 8; j++) acc[i][j] = 0.f;

    const int ldaN = (A2 != nullptr) ? 512 : K;

    for (int k0 = 0; k0 < K; k0 += 8) {
        // load A tile
        {
            int m = row0 + la_r;
            int kk = k0 + la_k;
            float4 v = make_float4(0.f, 0.f, 0.f, 0.f);
            if (m < M) {
                const float* Ap = A;
                int ka = kk;
                if (A2 != nullptr && kk >= 512) { Ap = A2; ka = kk - 512; }
                int mp = m;
                if (revT) mp = (511 - (m >> 6)) * 64 + (m & 63);
                v = *(const float4*)(Ap + (size_t)mp * ldaN + ka);
            }
            As[la_k + 0][la_r] = v.x;
            As[la_k + 1][la_r] = v.y;
            As[la_k + 2][la_r] = v.z;
            As[la_k + 3][la_r] = v.w;
        }
        // load B tile
        {
            int kk = k0 + lb_k;
            float4 v = *(const float4*)(Bm + (size_t)kk * Nc + col0 + lb_c);
            *(float4*)&Bs[lb_k][lb_c] = v;
        }
        __syncthreads();
#pragma unroll
        for (int kk = 0; kk < 8; kk++) {
            float a[8], b[8];
            *(float4*)&a[0] = *(const float4*)&As[kk][tr];
            *(float4*)&a[4] = *(const float4*)&As[kk][tr + 4];
            *(float4*)&b[0] = *(const float4*)&Bs[kk][tc];
            *(float4*)&b[4] = *(const float4*)&Bs[kk][tc + 4];
#pragma unroll
            for (int i = 0; i < 8; i++)
#pragma unroll
                for (int j = 0; j < 8; j++)
                    acc[i][j] = fmaf(a[i], b[j], acc[i][j]);
        }
        __syncthreads();
    }

    // epilogue
#pragma unroll
    for (int i = 0; i < 8; i++) {
        int m = row0 + tr + i;
        if (m >= M) continue;
        size_t base = (size_t)m * Nc + col0 + tc;
        int rm = (m & 63) * Nc;
#pragma unroll
        for (int j = 0; j < 8; j++) {
            float v = acc[i][j];
            int c = col0 + tc + j;
            if (bias)   v += bias[c];
            if (rowAdd) v += rowAdd[rm + c];
            C[base + j] = v;
        }
    }
}

// ---------------------------------------------------------------------------
// Persistent GRU scan.
//   Per step s: g = h_{s-1} @ Wh (+bh); gates; h_s -> OUT[map(s)].
//   h read from OUT[map(s-1)] (h0 = 0). XW precomputed: XW[s] already in
//   processing order (backward direction has its xW precomputed reversed).
//   Each CTA owns U hidden units (3U Wh columns resident in smem).
//   Threads: NPOS positions (8 rowgroups x CG colgroups, TN=6 cols each)
//            x KS K-slices = 256.
// ---------------------------------------------------------------------------
struct GruArgs {
    const float* XW;   // [T, 64, 1536]
    const float* Wh;   // [512, 1536]
    const float* bh;   // [1536]
    float* OUT;        // [T, 64, 512]
    int rev;           // 1 => out index = 511 - s
    int bar_id;
};

#define HSTRIDE 513

template <int U, int CG, int KS>
__global__ __launch_bounds__(256) void gru_kernel(GruArgs a0, GruArgs a1, int ctas_per_group)
{
    constexpr int COLS = 3 * U;
    constexpr int TN = COLS / CG;      // 6
    constexpr int NPOS = 8 * CG;
    constexpr int KD = 512 / KS;

    extern __shared__ float sm[];
    float* whs  = sm;                          // [512][COLS]
    float* hs   = whs + 512 * COLS;            // [64][HSTRIDE]
    float* part = hs + 64 * HSTRIDE;           // [KS][64][COLS]
    float* bhs  = part + KS * 64 * COLS;       // [COLS]

    const int tid = threadIdx.x;
    const int group = blockIdx.x / ctas_per_group;
    const GruArgs a = (group == 0) ? a0 : a1;
    const int u0 = (blockIdx.x % ctas_per_group) * U;

    // load Wh slice + bh slice (once)
    for (int idx = tid; idx < 512 * COLS; idx += 256) {
        int d = idx / COLS, c = idx % COLS;
        int u = c / 3, g = c - u * 3;
        whs[idx] = a.Wh[(size_t)d * G3 + g * 512 + (u0 + u)];
    }
    if (tid < COLS) {
        int u = tid / 3, g = tid - u * 3;
        bhs[tid] = a.bh[g * 512 + (u0 + u)];
    }

    const int pos = tid % NPOS;
    const int ks  = tid / NPOS;
    const int rg  = pos / CG;            // 0..7  (rows rg, rg+8, ..., rg+56)
    const int cg  = pos % CG;
    const int c0  = cg * TN;
    const int d0  = ks * KD;

    for (int s = 0; s < TT; s++) {
        // ---- stage h into smem ----
        if (s == 0) {
            for (int idx = tid; idx < 64 * HSTRIDE; idx += 256) hs[idx] = 0.f;
        } else {
            int pidx = a.rev ? (TT - s) : (s - 1);
            const float* hsrc = a.OUT + (size_t)pidx * NBATCH * HID;
            for (int i4 = tid; i4 < (64 * 512) / 4; i4 += 256) {
                float4 v = ((const float4*)hsrc)[i4];
                int fi = i4 * 4;
                int r = fi >> 9, d = fi & 511;
                float* dst = &hs[r * HSTRIDE + d];
                dst[0] = v.x; dst[1] = v.y; dst[2] = v.z; dst[3] = v.w;
            }
        }
        __syncthreads();

        // ---- partial GEMM: [64,512] @ whs[512,COLS] over K slice ----
        float acc[8][TN];
#pragma unroll
        for (int i = 0; i < 8; i++)
#pragma unroll
            for (int j = 0; j < TN; j++) acc[i][j] = 0.f;

        const float* wrow = whs + d0 * COLS + c0;
        const float* hrow = hs + rg * HSTRIDE + d0;
#pragma unroll 4
        for (int d = 0; d < KD; d++) {
            float bv[TN];
#pragma unroll
            for (int j = 0; j < TN; j++) bv[j] = wrow[j];
#pragma unroll
            for (int i = 0; i < 8; i++) {
                float av = hrow[i * (8 * HSTRIDE)];
#pragma unroll
                for (int j = 0; j < TN; j++)
                    acc[i][j] = fmaf(av, bv[j], acc[i][j]);
            }
            wrow += COLS;
            hrow += 1;
        }
#pragma unroll
        for (int i = 0; i < 8; i++) {
            int row = rg + 8 * i;
            float* pp = &part[((size_t)ks * 64 + row) * COLS + c0];
#pragma unroll
            for (int j = 0; j < TN; j++) pp[j] = acc[i][j];
        }
        __syncthreads();

        // ---- reduce K slices + gates + write h ----
        int oidx = a.rev ? (TT - 1 - s) : s;
        for (int it = tid; it < 64 * U; it += 256) {
            int row = it / U;
            int u   = it - row * U;
            int cb  = u * 3;
            float gr = 0.f, gz = 0.f, gn = 0.f;
#pragma unroll
            for (int k2 = 0; k2 < KS; k2++) {
                const float* pp = &part[((size_t)k2 * 64 + row) * COLS + cb];
                gr += pp[0]; gz += pp[1]; gn += pp[2];
            }
            int j = u0 + u;
            const float* xwrow = a.XW + ((size_t)s * NBATCH + row) * G3;
            float xr = xwrow[j], xz = xwrow[512 + j], xn = xwrow[1024 + j];
            float r = 1.f / (1.f + expf(-(xr + gr + bhs[cb])));
            float z = 1.f / (1.f + expf(-(xz + gz + bhs[cb + 1])));
            float nn = tanhf(xn + r * (gn + bhs[cb + 2]));
            float hprev = hs[row * HSTRIDE + j];
            float hnew = (1.f - z) * nn + z * hprev;
            a.OUT[((size_t)oidx * NBATCH + row) * HID + j] = hnew;
        }

        // ---- publish + group barrier (also fences hs reuse) ----
        grid_barrier(a.bar_id, ctas_per_group);
    }
}

// ---------------------------------------------------------------------------
// msg: msg[n,j] = (sum_a h[b,a,j] - h[n,j]) / (A-1)
// ---------------------------------------------------------------------------
__global__ void msg_kernel(const float* __restrict__ h, float* __restrict__ msg)
{
    int idx = blockIdx.x * blockDim.x + threadIdx.x;
    if (idx >= NBATCH * HID) return;
    int n = idx >> 9, j = idx & 511;
    int b = n >> 3;
    float s = 0.f;
#pragma unroll
    for (int aa = 0; aa < AAGENT; aa++) s += h[((b << 3) + aa) * HID + j];
    msg[idx] = (s - h[n * HID + j]) * (1.f / (AAGENT - 1));
}

// last_h_of_first_agent: out[b, j] = OUT[T-1, b*A + 0, j]
__global__ void lasth_kernel(const float* __restrict__ OUT, float* __restrict__ dst)
{
    int idx = blockIdx.x * blockDim.x + threadIdx.x;
    if (idx >= BBATCH * HID) return;
    int b = idx >> 9, j = idx & 511;
    dst[idx] = OUT[((size_t)(TT - 1) * NBATCH + b * AAGENT) * HID + j];
}

// ---------------------------------------------------------------------------
// launch
// ---------------------------------------------------------------------------
extern "C" void kernel_launch(void* const* d_in, const int* in_sizes, int n_in,
                              void* d_out, int out_size)
{
    const float* article = (const float*)d_in[0];
    // d_in[1] = seq_lenghts (all == T; unused)
    const float* Wx_f = (const float*)d_in[2];
    const float* Wh_f = (const float*)d_in[3];
    const float* bx_f = (const float*)d_in[4];
    const float* bh_f = (const float*)d_in[5];
    const float* Wx_b = (const float*)d_in[6];
    const float* Wh_b = (const float*)d_in[7];
    const float* bx_b = (const float*)d_in[8];
    const float* bh_b = (const float*)d_in[9];
    const float* Wp   = (const float*)d_in[10];
    const float* bp   = (const float*)d_in[11];
    const float* Wm   = (const float*)d_in[12];
    const float* bm   = (const float*)d_in[13];
    const float* Wx_c = (const float*)d_in[14];
    const float* Wh_c = (const float*)d_in[15];
    const float* bx_c = (const float*)d_in[16];
    const float* bh_c = (const float*)d_in[17];

    float *XW1, *XW2, *ENCF, *ENCB, *ENC, *hsm, *msg, *msgp;
    cudaGetSymbolAddress((void**)&XW1,  g_XW1);
    cudaGetSymbolAddress((void**)&XW2,  g_XW2);
    cudaGetSymbolAddress((void**)&ENCF, g_ENCF);
    cudaGetSymbolAddress((void**)&ENCB, g_ENCB);
    cudaGetSymbolAddress((void**)&ENC,  g_ENC);
    cudaGetSymbolAddress((void**)&hsm,  g_hsm);
    cudaGetSymbolAddress((void**)&msg,  g_msg);
    cudaGetSymbolAddress((void**)&msgp, g_msgp);

    const int M = TT * NBATCH;
    const size_t SM8 = (size_t)(512 * 24 + 64 * HSTRIDE + 8 * 64 * 24 + 24) * 4;
    const size_t SM4 = (size_t)(512 * 12 + 64 * HSTRIDE + 16 * 64 * 12 + 12) * 4;
    cudaFuncSetAttribute((const void*)gru_kernel<8, 4, 8>,
                         cudaFuncAttributeMaxDynamicSharedMemorySize, (int)SM8);
    cudaFuncSetAttribute((const void*)gru_kernel<4, 2, 16>,
                         cudaFuncAttributeMaxDynamicSharedMemorySize, (int)SM4);

    // 1) xW precompute for both directions (backward reads time-reversed rows)
    sgemm<<<dim3(G3 / 128, M / 128), 256>>>(article, nullptr, Wx_f, bx_f, nullptr,
                                            XW1, M, DIN, G3, 0);
    sgemm<<<dim3(G3 / 128, M / 128), 256>>>(article, nullptr, Wx_b, bx_b, nullptr,
                                            XW2, M, DIN, G3, 1);

    // 2) bidirectional recurrence (two 64-CTA barrier groups in one launch)
    GruArgs af{XW1, Wh_f, bh_f, ENCF, 0, 0};
    GruArgs ab{XW2, Wh_b, bh_b, ENCB, 1, 1};
    gru_kernel<8, 4, 8><<<128, 256, SM8>>>(af, ab, 64);

    // 3) projection of per-step encodings and of final hidden
    sgemm<<<dim3(HID / 128, M / 128), 256>>>(ENCF, ENCB, Wp, bp, nullptr,
                                             ENC, M, 2 * HID, HID, 0);
    sgemm<<<dim3(HID / 128, 1), 256>>>(ENCF + (size_t)(TT - 1) * NBATCH * HID, ENCB,
                                       Wp, bp, nullptr, hsm, NBATCH, 2 * HID, HID, 0);

    // 4) communication layers
    for (int l = 0; l < LLAYER; l++) {
        const float* hsrc = (l == 0) ? hsm : (ENC + (size_t)(TT - 1) * NBATCH * HID);
        msg_kernel<<<(NBATCH * HID) / 256, 256>>>(hsrc, msg);
        // msgp = msg @ Wm[512:,:] + bm   (tiny)
        sgemm<<<dim3(HID / 128, 1), 256>>>(msg, nullptr, Wm + (size_t)512 * HID, bm,
                                           nullptr, msgp, NBATCH, HID, HID, 0);
        // NXT = enc @ Wm[:512,:] + msgp[row]
        sgemm<<<dim3(HID / 128, M / 128), 256>>>(ENC, nullptr, Wm, nullptr, msgp,
                                                 XW2, M, HID, HID, 0);
        // XW_c = NXT @ Wx_c[l] + bx_c[l]
        sgemm<<<dim3(G3 / 128, M / 128), 256>>>(XW2, nullptr,
                                                Wx_c + (size_t)l * HID * G3,
                                                bx_c + (size_t)l * G3, nullptr,
                                                XW1, M, HID, G3, 0);
        float* outp = (l == LLAYER - 1) ? (float*)d_out : ENC;
        GruArgs ac{XW1, Wh_c + (size_t)l * HID * G3, bh_c + (size_t)l * G3,
                   outp, 0, 2 + l};
        gru_kernel<4, 2, 16><<<128, 256, SM4>>>(ac, ac, 128);
    }

    // 5) tail output: last hidden of first agent per batch
    lasth_kernel<<<(BBATCH * HID + 255) / 256, 256>>>(
        (const float*)d_out, (float*)d_out + (size_t)TT * NBATCH * HID);
}

// round 2
// speedup vs baseline: 1.1338x; 1.1338x over previous
#include <cuda_runtime.h>
#include <cuda_bf16.h>
#include <math.h>
#include <stdint.h>

// Problem constants
#define TT 512
#define NBATCH 64      // B*A
#define HID 512
#define DIN 512
#define G3 1536        // 3*HID
#define BBATCH 8
#define AAGENT 8
#define LLAYER 2

// ---------------------------------------------------------------------------
// Scratch (device globals; no allocations allowed)
// ---------------------------------------------------------------------------
__device__ float g_XW1[(size_t)TT * NBATCH * G3];   // 192 MB
__device__ float g_XW2[(size_t)TT * NBATCH * G3];   // 192 MB
__device__ float g_ENCF[(size_t)TT * NBATCH * HID]; // 64 MB
__device__ float g_ENCB[(size_t)TT * NBATCH * HID]; // 64 MB (stored at original t index)
__device__ float g_ENC [(size_t)TT * NBATCH * HID]; // 64 MB
__device__ float g_hsm [NBATCH * HID];
__device__ float g_msg [NBATCH * HID];
__device__ float g_msgp[NBATCH * HID];
__device__ unsigned g_bar_count[8];
__device__ unsigned g_bar_gen[8];

// ---------------------------------------------------------------------------
// Software grid barrier (per-group). All CTAs of a group must be co-resident.
// ---------------------------------------------------------------------------
__device__ __forceinline__ void grid_barrier(int id, int ncta) {
    __threadfence();
    __syncthreads();
    if (threadIdx.x == 0) {
        volatile unsigned* genp = &g_bar_gen[id];
        unsigned g = *genp;
        __threadfence();
        unsigned old = atomicAdd(&g_bar_count[id], 1u);
        if (old == (unsigned)(ncta - 1)) {
            g_bar_count[id] = 0;
            __threadfence();
            *genp = g + 1u;
        } else {
            while (*genp == g) { }
        }
        __threadfence();
    }
    __syncthreads();
}

// ---------------------------------------------------------------------------
// Tensor-core GEMM (bf16 3-term split ~= fp32 precision).
//   C[M,Nc] = op(A) @ B (+ bias[col]) (+ rowAdd[m%64, col])
//   A row-major f32. If A2 != null: logical K = 1024, k<512 from A, k>=512
//   from A2 (both lda=512). If revT: A physical row = (511 - m/64)*64 + m%64.
//   B row-major f32 [K, Nc]. Tile: 128x128xBK32, 256 threads, 8 warps of
//   64x32, mma.sync m16n8k16 bf16 with hi/lo split (3 mma passes).
// ---------------------------------------------------------------------------
__device__ __forceinline__ uint32_t sptr(const void* p) {
    return (uint32_t)__cvta_generic_to_shared(p);
}

#define LDSM_X4(R0, R1, R2, R3, ADDR)                                          \
    asm volatile("ldmatrix.sync.aligned.m8n8.x4.shared.b16 {%0,%1,%2,%3},[%4];"\
                 : "=r"(R0), "=r"(R1), "=r"(R2), "=r"(R3) : "r"(ADDR))

#define LDSM_X4T(R0, R1, R2, R3, ADDR)                                         \
    asm volatile("ldmatrix.sync.aligned.m8n8.x4.trans.shared.b16 "             \
                 "{%0,%1,%2,%3},[%4];"                                         \
                 : "=r"(R0), "=r"(R1), "=r"(R2), "=r"(R3) : "r"(ADDR))

#define MMA16816(C0, C1, C2, C3, A0, A1, A2_, A3, B0, B1)                      \
    asm volatile("mma.sync.aligned.m16n8k16.row.col.f32.bf16.bf16.f32 "        \
                 "{%0,%1,%2,%3},{%4,%5,%6,%7},{%8,%9},{%0,%1,%2,%3};"          \
                 : "+f"(C0), "+f"(C1), "+f"(C2), "+f"(C3)                      \
                 : "r"(A0), "r"(A1), "r"(A2_), "r"(A3), "r"(B0), "r"(B1))

__global__ __launch_bounds__(256) void tgemm(
    const float* __restrict__ A, const float* __restrict__ A2,
    const float* __restrict__ Bm, const float* __restrict__ bias,
    const float* __restrict__ rowAdd, float* __restrict__ C,
    int M, int K, int Nc, int revT)
{
    // Tiled 8x8 layouts: tile(m8,k8) for A = (k8*16 + m8), 64 bf16 each.
    __shared__ __nv_bfloat16 Ah[4096], Al[4096], Bh[4096], Bl[4096];

    const int tid  = threadIdx.x;
    const int lane = tid & 31;
    const int warp = tid >> 5;
    const int warpM = warp >> 2;      // 0..1  (64 rows)
    const int warpN = warp & 3;       // 0..3  (32 cols)
    const int row0 = blockIdx.y * 128;
    const int col0 = blockIdx.x * 128;
    const int lda = (A2 != nullptr) ? 512 : K;

    float acc[4][4][4];
#pragma unroll
    for (int mt = 0; mt < 4; mt++)
#pragma unroll
        for (int nt = 0; nt < 4; nt++)
#pragma unroll
            for (int q = 0; q < 4; q++) acc[mt][nt][q] = 0.f;

    // ldmatrix source addresses (byte), fixed per thread modulo kc/mt/np
    const int g = lane >> 3, r = lane & 7;

    for (int k0 = 0; k0 < K; k0 += 32) {
        // ---- stage A tile (128x32) as bf16 hi/lo ----
#pragma unroll
        for (int e = 0; e < 8; e++) {
            int id = e * 256 + tid;
            int m  = id >> 4;
            int k  = (id & 15) << 1;
            float2 v = make_float2(0.f, 0.f);
            int gm = row0 + m;
            if (gm < M) {
                int kk = k0 + k;
                const float* Ap = A;
                int ka = kk;
                if (A2 != nullptr && kk >= 512) { Ap = A2; ka = kk - 512; }
                int mp = gm;
                if (revT) mp = (511 - (gm >> 6)) * 64 + (gm & 63);
                v = *(const float2*)(Ap + (size_t)mp * lda + ka);
            }
            __nv_bfloat16 h0 = __float2bfloat16(v.x);
            __nv_bfloat16 h1 = __float2bfloat16(v.y);
            __nv_bfloat16 l0 = __float2bfloat16(v.x - __bfloat162float(h0));
            __nv_bfloat16 l1 = __float2bfloat16(v.y - __bfloat162float(h1));
            int off = (((k >> 3) << 4) + (m >> 3)) * 64 + ((m & 7) << 3) + (k & 7);
            __nv_bfloat162 ph; ph.x = h0; ph.y = h1;
            __nv_bfloat162 pl; pl.x = l0; pl.y = l1;
            *(__nv_bfloat162*)(Ah + off) = ph;
            *(__nv_bfloat162*)(Al + off) = pl;
        }
        // ---- stage B tile (32x128) ----
#pragma unroll
        for (int e = 0; e < 8; e++) {
            int id = e * 256 + tid;
            int k  = id >> 6;
            int n  = (id & 63) << 1;
            float2 v = *(const float2*)(Bm + (size_t)(k0 + k) * Nc + col0 + n);
            __nv_bfloat16 h0 = __float2bfloat16(v.x);
            __nv_bfloat16 h1 = __float2bfloat16(v.y);
            __nv_bfloat16 l0 = __float2bfloat16(v.x - __bfloat162float(h0));
            __nv_bfloat16 l1 = __float2bfloat16(v.y - __bfloat162float(h1));
            int off = (((k >> 3) << 4) + (n >> 3)) * 64 + ((k & 7) << 3) + (n & 7);
            __nv_bfloat162 ph; ph.x = h0; ph.y = h1;
            __nv_bfloat162 pl; pl.x = l0; pl.y = l1;
            *(__nv_bfloat162*)(Bh + off) = ph;
            *(__nv_bfloat162*)(Bl + off) = pl;
        }
        __syncthreads();

#pragma unroll
        for (int kc = 0; kc < 2; kc++) {
            // B fragments for all 4 ntiles (hi and lo)
            uint32_t bh[8], bl[8];
#pragma unroll
            for (int np = 0; np < 2; np++) {
                int k8 = kc * 2 + (g & 1);
                int n8 = warpN * 4 + np * 2 + (g >> 1);
                int elem = (k8 * 16 + n8) * 64 + r * 8;
                uint32_t ad = sptr(Bh + elem);
                LDSM_X4T(bh[np * 4 + 0], bh[np * 4 + 1],
                         bh[np * 4 + 2], bh[np * 4 + 3], ad);
                ad = sptr(Bl + elem);
                LDSM_X4T(bl[np * 4 + 0], bl[np * 4 + 1],
                         bl[np * 4 + 2], bl[np * 4 + 3], ad);
            }
#pragma unroll
            for (int mt = 0; mt < 4; mt++) {
                int m8 = warpM * 8 + mt * 2 + (g & 1);
                int k8 = kc * 2 + (g >> 1);
                int elem = (k8 * 16 + m8) * 64 + r * 8;
                uint32_t ah[4], al[4];
                uint32_t ad = sptr(Ah + elem);
                LDSM_X4(ah[0], ah[1], ah[2], ah[3], ad);
                ad = sptr(Al + elem);
                LDSM_X4(al[0], al[1], al[2], al[3], ad);
#pragma unroll
                for (int nt = 0; nt < 4; nt++) {
                    float* c = acc[mt][nt];
                    MMA16816(c[0], c[1], c[2], c[3],
                             ah[0], ah[1], ah[2], ah[3], bh[nt * 2], bh[nt * 2 + 1]);
                    MMA16816(c[0], c[1], c[2], c[3],
                             ah[0], ah[1], ah[2], ah[3], bl[nt * 2], bl[nt * 2 + 1]);
                    MMA16816(c[0], c[1], c[2], c[3],
                             al[0], al[1], al[2], al[3], bh[nt * 2], bh[nt * 2 + 1]);
                }
            }
        }
        __syncthreads();
    }

    // ---- epilogue ----
#pragma unroll
    for (int mt = 0; mt < 4; mt++) {
#pragma unroll
        for (int nt = 0; nt < 4; nt++) {
            int rA = row0 + warpM * 64 + mt * 16 + (lane >> 2);
            int cg = col0 + warpN * 32 + nt * 8 + ((lane & 3) << 1);
            float b0 = 0.f, b1 = 0.f;
            if (bias) { b0 = bias[cg]; b1 = bias[cg + 1]; }
#pragma unroll
            for (int half = 0; half < 2; half++) {
                int m = rA + half * 8;
                if (m >= M) continue;
                float v0 = acc[mt][nt][half * 2 + 0] + b0;
                float v1 = acc[mt][nt][half * 2 + 1] + b1;
                if (rowAdd) {
                    int rm = (m & 63) * Nc;
                    v0 += rowAdd[rm + cg];
                    v1 += rowAdd[rm + cg + 1];
                }
                float2 o; o.x = v0; o.y = v1;
                *(float2*)(C + (size_t)m * Nc + cg) = o;
            }
        }
    }
}

// ---------------------------------------------------------------------------
// Persistent GRU scan (unchanged from R1).
// ---------------------------------------------------------------------------
struct GruArgs {
    const float* XW;   // [T, 64, 1536]
    const float* Wh;   // [512, 1536]
    const float* bh;   // [1536]
    float* OUT;        // [T, 64, 512]
    int rev;           // 1 => out index = 511 - s
    int bar_id;
};

#define HSTRIDE 513

template <int U, int CG, int KS>
__global__ __launch_bounds__(256) void gru_kernel(GruArgs a0, GruArgs a1, int ctas_per_group)
{
    constexpr int COLS = 3 * U;
    constexpr int TN = COLS / CG;      // 6
    constexpr int NPOS = 8 * CG;
    constexpr int KD = 512 / KS;

    extern __shared__ float sm[];
    float* whs  = sm;                          // [512][COLS]
    float* hs   = whs + 512 * COLS;            // [64][HSTRIDE]
    float* part = hs + 64 * HSTRIDE;           // [KS][64][COLS]
    float* bhs  = part + KS * 64 * COLS;       // [COLS]

    const int tid = threadIdx.x;
    const int group = blockIdx.x / ctas_per_group;
    const GruArgs a = (group == 0) ? a0 : a1;
    const int u0 = (blockIdx.x % ctas_per_group) * U;

    for (int idx = tid; idx < 512 * COLS; idx += 256) {
        int d = idx / COLS, c = idx % COLS;
        int u = c / 3, gg = c - u * 3;
        whs[idx] = a.Wh[(size_t)d * G3 + gg * 512 + (u0 + u)];
    }
    if (tid < COLS) {
        int u = tid / 3, gg = tid - u * 3;
        bhs[tid] = a.bh[gg * 512 + (u0 + u)];
    }

    const int pos = tid % NPOS;
    const int ks  = tid / NPOS;
    const int rg  = pos / CG;
    const int cg  = pos % CG;
    const int c0  = cg * TN;
    const int d0  = ks * KD;

    for (int s = 0; s < TT; s++) {
        if (s == 0) {
            for (int idx = tid; idx < 64 * HSTRIDE; idx += 256) hs[idx] = 0.f;
        } else {
            int pidx = a.rev ? (TT - s) : (s - 1);
            const float* hsrc = a.OUT + (size_t)pidx * NBATCH * HID;
            for (int i4 = tid; i4 < (64 * 512) / 4; i4 += 256) {
                float4 v = ((const float4*)hsrc)[i4];
                int fi = i4 * 4;
                int rr = fi >> 9, d = fi & 511;
                float* dst = &hs[rr * HSTRIDE + d];
                dst[0] = v.x; dst[1] = v.y; dst[2] = v.z; dst[3] = v.w;
            }
        }
        __syncthreads();

        float acc[8][TN];
#pragma unroll
        for (int i = 0; i < 8; i++)
#pragma unroll
            for (int j = 0; j < TN; j++) acc[i][j] = 0.f;

        const float* wrow = whs + d0 * COLS + c0;
        const float* hrow = hs + rg * HSTRIDE + d0;
#pragma unroll 4
        for (int d = 0; d < KD; d++) {
            float bv[TN];
#pragma unroll
            for (int j = 0; j < TN; j++) bv[j] = wrow[j];
#pragma unroll
            for (int i = 0; i < 8; i++) {
                float av = hrow[i * (8 * HSTRIDE)];
#pragma unroll
                for (int j = 0; j < TN; j++)
                    acc[i][j] = fmaf(av, bv[j], acc[i][j]);
            }
            wrow += COLS;
            hrow += 1;
        }
#pragma unroll
        for (int i = 0; i < 8; i++) {
            int row = rg + 8 * i;
            float* pp = &part[((size_t)ks * 64 + row) * COLS + c0];
#pragma unroll
            for (int j = 0; j < TN; j++) pp[j] = acc[i][j];
        }
        __syncthreads();

        int oidx = a.rev ? (TT - 1 - s) : s;
        for (int it = tid; it < 64 * U; it += 256) {
            int row = it / U;
            int u   = it - row * U;
            int cb  = u * 3;
            float gr = 0.f, gz = 0.f, gn = 0.f;
#pragma unroll
            for (int k2 = 0; k2 < KS; k2++) {
                const float* pp = &part[((size_t)k2 * 64 + row) * COLS + cb];
                gr += pp[0]; gz += pp[1]; gn += pp[2];
            }
            int j = u0 + u;
            const float* xwrow = a.XW + ((size_t)s * NBATCH + row) * G3;
            float xr = xwrow[j], xz = xwrow[512 + j], xn = xwrow[1024 + j];
            float rr = 1.f / (1.f + expf(-(xr + gr + bhs[cb])));
            float zz = 1.f / (1.f + expf(-(xz + gz + bhs[cb + 1])));
            float nn = tanhf(xn + rr * (gn + bhs[cb + 2]));
            float hprev = hs[row * HSTRIDE + j];
            float hnew = (1.f - zz) * nn + zz * hprev;
            a.OUT[((size_t)oidx * NBATCH + row) * HID + j] = hnew;
        }

        grid_barrier(a.bar_id, ctas_per_group);
    }
}

// ---------------------------------------------------------------------------
// msg: msg[n,j] = (sum_a h[b,a,j] - h[n,j]) / (A-1)
// ---------------------------------------------------------------------------
__global__ void msg_kernel(const float* __restrict__ h, float* __restrict__ msg)
{
    int idx = blockIdx.x * blockDim.x + threadIdx.x;
    if (idx >= NBATCH * HID) return;
    int n = idx >> 9, j = idx & 511;
    int b = n >> 3;
    float s = 0.f;
#pragma unroll
    for (int aa = 0; aa < AAGENT; aa++) s += h[((b << 3) + aa) * HID + j];
    msg[idx] = (s - h[n * HID + j]) * (1.f / (AAGENT - 1));
}

__global__ void lasth_kernel(const float* __restrict__ OUT, float* __restrict__ dst)
{
    int idx = blockIdx.x * blockDim.x + threadIdx.x;
    if (idx >= BBATCH * HID) return;
    int b = idx >> 9, j = idx & 511;
    dst[idx] = OUT[((size_t)(TT - 1) * NBATCH + b * AAGENT) * HID + j];
}

// ---------------------------------------------------------------------------
// launch
// ---------------------------------------------------------------------------
extern "C" void kernel_launch(void* const* d_in, const int* in_sizes, int n_in,
                              void* d_out, int out_size)
{
    const float* article = (const float*)d_in[0];
    const float* Wx_f = (const float*)d_in[2];
    const float* Wh_f = (const float*)d_in[3];
    const float* bx_f = (const float*)d_in[4];
    const float* bh_f = (const float*)d_in[5];
    const float* Wx_b = (const float*)d_in[6];
    const float* Wh_b = (const float*)d_in[7];
    const float* bx_b = (const float*)d_in[8];
    const float* bh_b = (const float*)d_in[9];
    const float* Wp   = (const float*)d_in[10];
    const float* bp   = (const float*)d_in[11];
    const float* Wm   = (const float*)d_in[12];
    const float* bm   = (const float*)d_in[13];
    const float* Wx_c = (const float*)d_in[14];
    const float* Wh_c = (const float*)d_in[15];
    const float* bx_c = (const float*)d_in[16];
    const float* bh_c = (const float*)d_in[17];

    float *XW1, *XW2, *ENCF, *ENCB, *ENC, *hsm, *msg, *msgp;
    cudaGetSymbolAddress((void**)&XW1,  g_XW1);
    cudaGetSymbolAddress((void**)&XW2,  g_XW2);
    cudaGetSymbolAddress((void**)&ENCF, g_ENCF);
    cudaGetSymbolAddress((void**)&ENCB, g_ENCB);
    cudaGetSymbolAddress((void**)&ENC,  g_ENC);
    cudaGetSymbolAddress((void**)&hsm,  g_hsm);
    cudaGetSymbolAddress((void**)&msg,  g_msg);
    cudaGetSymbolAddress((void**)&msgp, g_msgp);

    const int M = TT * NBATCH;
    const size_t SM8 = (size_t)(512 * 24 + 64 * HSTRIDE + 8 * 64 * 24 + 24) * 4;
    const size_t SM4 = (size_t)(512 * 12 + 64 * HSTRIDE + 16 * 64 * 12 + 12) * 4;
    cudaFuncSetAttribute((const void*)gru_kernel<8, 4, 8>,
                         cudaFuncAttributeMaxDynamicSharedMemorySize, (int)SM8);
    cudaFuncSetAttribute((const void*)gru_kernel<4, 2, 16>,
                         cudaFuncAttributeMaxDynamicSharedMemorySize, (int)SM4);

    // 1) xW precompute for both directions (backward reads time-reversed rows)
    tgemm<<<dim3(G3 / 128, M / 128), 256>>>(article, nullptr, Wx_f, bx_f, nullptr,
                                            XW1, M, DIN, G3, 0);
    tgemm<<<dim3(G3 / 128, M / 128), 256>>>(article, nullptr, Wx_b, bx_b, nullptr,
                                            XW2, M, DIN, G3, 1);

    // 2) bidirectional recurrence (two 64-CTA barrier groups in one launch)
    GruArgs af{XW1, Wh_f, bh_f, ENCF, 0, 0};
    GruArgs ab{XW2, Wh_b, bh_b, ENCB, 1, 1};
    gru_kernel<8, 4, 8><<<128, 256, SM8>>>(af, ab, 64);

    // 3) projection of per-step encodings and of final hidden
    tgemm<<<dim3(HID / 128, M / 128), 256>>>(ENCF, ENCB, Wp, bp, nullptr,
                                             ENC, M, 2 * HID, HID, 0);
    tgemm<<<dim3(HID / 128, 1), 256>>>(ENCF + (size_t)(TT - 1) * NBATCH * HID, ENCB,
                                       Wp, bp, nullptr, hsm, NBATCH, 2 * HID, HID, 0);

    // 4) communication layers
    for (int l = 0; l < LLAYER; l++) {
        const float* hsrc = (l == 0) ? hsm : (ENC + (size_t)(TT - 1) * NBATCH * HID);
        msg_kernel<<<(NBATCH * HID) / 256, 256>>>(hsrc, msg);
        tgemm<<<dim3(HID / 128, 1), 256>>>(msg, nullptr, Wm + (size_t)512 * HID, bm,
                                           nullptr, msgp, NBATCH, HID, HID, 0);
        tgemm<<<dim3(HID / 128, M / 128), 256>>>(ENC, nullptr, Wm, nullptr, msgp,
                                                 XW2, M, HID, HID, 0);
        tgemm<<<dim3(G3 / 128, M / 128), 256>>>(XW2, nullptr,
                                                Wx_c + (size_t)l * HID * G3,
                                                bx_c + (size_t)l * G3, nullptr,
                                                XW1, M, HID, G3, 0);
        float* outp = (l == LLAYER - 1) ? (float*)d_out : ENC;
        GruArgs ac{XW1, Wh_c + (size_t)l * HID * G3, bh_c + (size_t)l * G3,
                   outp, 0, 2 + l};
        gru_kernel<4, 2, 16><<<128, 256, SM4>>>(ac, ac, 128);
    }

    // 5) tail output: last hidden of first agent per batch
    lasth_kernel<<<(BBATCH * HID + 255) / 256, 256>>>(
        (const float*)d_out, (float*)d_out + (size_t)TT * NBATCH * HID);
}

// round 3
// speedup vs baseline: 1.5457x; 1.3633x over previous
#include <cuda_runtime.h>
#include <cuda_bf16.h>
#include <math.h>
#include <stdint.h>

// Problem constants
#define TT 512
#define NBATCH 64      // B*A
#define HID 512
#define DIN 512
#define G3 1536        // 3*HID
#define BBATCH 8
#define AAGENT 8
#define LLAYER 2

// ---------------------------------------------------------------------------
// Scratch (device globals; no allocations allowed)
// ---------------------------------------------------------------------------
__device__ float g_XW1[(size_t)TT * NBATCH * G3];   // 192 MB
__device__ float g_XW2[(size_t)TT * NBATCH * G3];   // 192 MB
__device__ float g_ENCF[(size_t)TT * NBATCH * HID]; // 64 MB
__device__ float g_ENCB[(size_t)TT * NBATCH * HID]; // 64 MB
__device__ float g_ENC [(size_t)TT * NBATCH * HID]; // 64 MB
__device__ float g_hsm [NBATCH * HID];
__device__ float g_msg [NBATCH * HID];
__device__ float g_msgp[NBATCH * HID];
__device__ __nv_bfloat16 g_hHiA[NBATCH * HID];      // tiled bf16 h (group A)
__device__ __nv_bfloat16 g_hLoA[NBATCH * HID];
__device__ __nv_bfloat16 g_hHiB[NBATCH * HID];      // tiled bf16 h (group B)
__device__ __nv_bfloat16 g_hLoB[NBATCH * HID];
__device__ unsigned g_bar_count[8];
__device__ unsigned g_bar_gen[8];

// ---------------------------------------------------------------------------
// Software grid barrier (per-group). All CTAs of a group must be co-resident.
// ---------------------------------------------------------------------------
__device__ __forceinline__ void grid_barrier(int id, int ncta) {
    __threadfence();
    __syncthreads();
    if (threadIdx.x == 0) {
        volatile unsigned* genp = &g_bar_gen[id];
        unsigned g = *genp;
        __threadfence();
        unsigned old = atomicAdd(&g_bar_count[id], 1u);
        if (old == (unsigned)(ncta - 1)) {
            g_bar_count[id] = 0;
            __threadfence();
            *genp = g + 1u;
        } else {
            while (*genp == g) { }
        }
        __threadfence();
    }
    __syncthreads();
}

// ---------------------------------------------------------------------------
// mma helpers
// ---------------------------------------------------------------------------
__device__ __forceinline__ uint32_t sptr(const void* p) {
    return (uint32_t)__cvta_generic_to_shared(p);
}

#define LDSM_X4(R0, R1, R2, R3, ADDR)                                          \
    asm volatile("ldmatrix.sync.aligned.m8n8.x4.shared.b16 {%0,%1,%2,%3},[%4];"\
                 : "=r"(R0), "=r"(R1), "=r"(R2), "=r"(R3) : "r"(ADDR))

#define LDSM_X4T(R0, R1, R2, R3, ADDR)                                         \
    asm volatile("ldmatrix.sync.aligned.m8n8.x4.trans.shared.b16 "             \
                 "{%0,%1,%2,%3},[%4];"                                         \
                 : "=r"(R0), "=r"(R1), "=r"(R2), "=r"(R3) : "r"(ADDR))

#define LDSM_X2T(R0, R1, ADDR)                                                 \
    asm volatile("ldmatrix.sync.aligned.m8n8.x2.trans.shared.b16 {%0,%1},[%2];"\
                 : "=r"(R0), "=r"(R1) : "r"(ADDR))

#define MMA16816(C0, C1, C2, C3, A0, A1, A2_, A3, B0, B1)                      \
    asm volatile("mma.sync.aligned.m16n8k16.row.col.f32.bf16.bf16.f32 "        \
                 "{%0,%1,%2,%3},{%4,%5,%6,%7},{%8,%9},{%0,%1,%2,%3};"          \
                 : "+f"(C0), "+f"(C1), "+f"(C2), "+f"(C3)                      \
                 : "r"(A0), "r"(A1), "r"(A2_), "r"(A3), "r"(B0), "r"(B1))

// ---------------------------------------------------------------------------
// Tensor-core GEMM (bf16 3-term split ~= fp32 precision). Unchanged from R2.
// ---------------------------------------------------------------------------
__global__ __launch_bounds__(256) void tgemm(
    const float* __restrict__ A, const float* __restrict__ A2,
    const float* __restrict__ Bm, const float* __restrict__ bias,
    const float* __restrict__ rowAdd, float* __restrict__ C,
    int M, int K, int Nc, int revT)
{
    __shared__ __nv_bfloat16 Ah[4096], Al[4096], Bh[4096], Bl[4096];

    const int tid  = threadIdx.x;
    const int lane = tid & 31;
    const int warp = tid >> 5;
    const int warpM = warp >> 2;
    const int warpN = warp & 3;
    const int row0 = blockIdx.y * 128;
    const int col0 = blockIdx.x * 128;
    const int lda = (A2 != nullptr) ? 512 : K;

    float acc[4][4][4];
#pragma unroll
    for (int mt = 0; mt < 4; mt++)
#pragma unroll
        for (int nt = 0; nt < 4; nt++)
#pragma unroll
            for (int q = 0; q < 4; q++) acc[mt][nt][q] = 0.f;

    const int g = lane >> 3, r = lane & 7;

    for (int k0 = 0; k0 < K; k0 += 32) {
#pragma unroll
        for (int e = 0; e < 8; e++) {
            int id = e * 256 + tid;
            int m  = id >> 4;
            int k  = (id & 15) << 1;
            float2 v = make_float2(0.f, 0.f);
            int gm = row0 + m;
            if (gm < M) {
                int kk = k0 + k;
                const float* Ap = A;
                int ka = kk;
                if (A2 != nullptr && kk >= 512) { Ap = A2; ka = kk - 512; }
                int mp = gm;
                if (revT) mp = (511 - (gm >> 6)) * 64 + (gm & 63);
                v = *(const float2*)(Ap + (size_t)mp * lda + ka);
            }
            __nv_bfloat16 h0 = __float2bfloat16(v.x);
            __nv_bfloat16 h1 = __float2bfloat16(v.y);
            __nv_bfloat16 l0 = __float2bfloat16(v.x - __bfloat162float(h0));
            __nv_bfloat16 l1 = __float2bfloat16(v.y - __bfloat162float(h1));
            int off = (((k >> 3) << 4) + (m >> 3)) * 64 + ((m & 7) << 3) + (k & 7);
            __nv_bfloat162 ph; ph.x = h0; ph.y = h1;
            __nv_bfloat162 pl; pl.x = l0; pl.y = l1;
            *(__nv_bfloat162*)(Ah + off) = ph;
            *(__nv_bfloat162*)(Al + off) = pl;
        }
#pragma unroll
        for (int e = 0; e < 8; e++) {
            int id = e * 256 + tid;
            int k  = id >> 6;
            int n  = (id & 63) << 1;
            float2 v = *(const float2*)(Bm + (size_t)(k0 + k) * Nc + col0 + n);
            __nv_bfloat16 h0 = __float2bfloat16(v.x);
            __nv_bfloat16 h1 = __float2bfloat16(v.y);
            __nv_bfloat16 l0 = __float2bfloat16(v.x - __bfloat162float(h0));
            __nv_bfloat16 l1 = __float2bfloat16(v.y - __bfloat162float(h1));
            int off = (((k >> 3) << 4) + (n >> 3)) * 64 + ((k & 7) << 3) + (n & 7);
            __nv_bfloat162 ph; ph.x = h0; ph.y = h1;
            __nv_bfloat162 pl; pl.x = l0; pl.y = l1;
            *(__nv_bfloat162*)(Bh + off) = ph;
            *(__nv_bfloat162*)(Bl + off) = pl;
        }
        __syncthreads();

#pragma unroll
        for (int kc = 0; kc < 2; kc++) {
            uint32_t bh[8], bl[8];
#pragma unroll
            for (int np = 0; np < 2; np++) {
                int k8 = kc * 2 + (g & 1);
                int n8 = warpN * 4 + np * 2 + (g >> 1);
                int elem = (k8 * 16 + n8) * 64 + r * 8;
                uint32_t ad = sptr(Bh + elem);
                LDSM_X4T(bh[np * 4 + 0], bh[np * 4 + 1],
                         bh[np * 4 + 2], bh[np * 4 + 3], ad);
                ad = sptr(Bl + elem);
                LDSM_X4T(bl[np * 4 + 0], bl[np * 4 + 1],
                         bl[np * 4 + 2], bl[np * 4 + 3], ad);
            }
#pragma unroll
            for (int mt = 0; mt < 4; mt++) {
                int m8 = warpM * 8 + mt * 2 + (g & 1);
                int k8 = kc * 2 + (g >> 1);
                int elem = (k8 * 16 + m8) * 64 + r * 8;
                uint32_t ah[4], al[4];
                uint32_t ad = sptr(Ah + elem);
                LDSM_X4(ah[0], ah[1], ah[2], ah[3], ad);
                ad = sptr(Al + elem);
                LDSM_X4(al[0], al[1], al[2], al[3], ad);
#pragma unroll
                for (int nt = 0; nt < 4; nt++) {
                    float* c = acc[mt][nt];
                    MMA16816(c[0], c[1], c[2], c[3],
                             ah[0], ah[1], ah[2], ah[3], bh[nt * 2], bh[nt * 2 + 1]);
                    MMA16816(c[0], c[1], c[2], c[3],
                             ah[0], ah[1], ah[2], ah[3], bl[nt * 2], bl[nt * 2 + 1]);
                    MMA16816(c[0], c[1], c[2], c[3],
                             al[0], al[1], al[2], al[3], bh[nt * 2], bh[nt * 2 + 1]);
                }
            }
        }
        __syncthreads();
    }

#pragma unroll
    for (int mt = 0; mt < 4; mt++) {
#pragma unroll
        for (int nt = 0; nt < 4; nt++) {
            int rA = row0 + warpM * 64 + mt * 16 + (lane >> 2);
            int cg = col0 + warpN * 32 + nt * 8 + ((lane & 3) << 1);
            float b0 = 0.f, b1 = 0.f;
            if (bias) { b0 = bias[cg]; b1 = bias[cg + 1]; }
#pragma unroll
            for (int half = 0; half < 2; half++) {
                int m = rA + half * 8;
                if (m >= M) continue;
                float v0 = acc[mt][nt][half * 2 + 0] + b0;
                float v1 = acc[mt][nt][half * 2 + 1] + b1;
                if (rowAdd) {
                    int rm = (m & 63) * Nc;
                    v0 += rowAdd[rm + cg];
                    v1 += rowAdd[rm + cg + 1];
                }
                float2 o; o.x = v0; o.y = v1;
                *(float2*)(C + (size_t)m * Nc + cg) = o;
            }
        }
    }
}

// ---------------------------------------------------------------------------
// Tensor-core persistent GRU scan.
//   Each CTA owns U=8 hidden units (24 Wh columns). Wh slice resident in smem
//   as bf16 hi/lo (ldmatrix-tiled). h circulates via global bf16 hi/lo scratch
//   in the SAME tiled layout (producer converts once; consumers do a linear
//   copy into smem). 8 warps = 4 mtiles x 2 K-halves; split-bf16 3-term mma.
// ---------------------------------------------------------------------------
struct GruArgs {
    const float* XW;        // [T, 64, 1536]
    const float* Wh;        // [512, 1536]
    const float* bh;        // [1536]
    float* OUT;             // [T, 64, 512]
    __nv_bfloat16* hHi;     // [64*512] tiled
    __nv_bfloat16* hLo;
    int rev;
    int bar_id;
};

// smem byte offsets
#define S_WHHI 0
#define S_WHLO 24576
#define S_HHI  49152
#define S_HLO  114688
#define S_PART 180224
#define S_HLOC 193024
#define S_BHS  195072
#define S_TOTAL 195200

__global__ __launch_bounds__(256) void gru_tc(GruArgs a0, GruArgs a1, int cpg)
{
    extern __shared__ char smraw[];
    __nv_bfloat16* WhHi = (__nv_bfloat16*)(smraw + S_WHHI);
    __nv_bfloat16* WhLo = (__nv_bfloat16*)(smraw + S_WHLO);
    __nv_bfloat16* hHi  = (__nv_bfloat16*)(smraw + S_HHI);
    __nv_bfloat16* hLo  = (__nv_bfloat16*)(smraw + S_HLO);
    float* part = (float*)(smraw + S_PART);   // [2][64*25]
    float* hloc = (float*)(smraw + S_HLOC);   // [64*8]
    float* bhs  = (float*)(smraw + S_BHS);    // [24]

    const int tid  = threadIdx.x;
    const int lane = tid & 31;
    const int warp = tid >> 5;
    const GruArgs a = (blockIdx.x / cpg == 0) ? a0 : a1;
    const int u0 = (blockIdx.x % cpg) * 8;

    // one-time: Wh slice -> smem bf16 hi/lo in tiled 8x8 layout (3 n8 blocks)
    for (int idx = tid; idx < 512 * 24; idx += 256) {
        int d = idx / 24, c = idx - d * 24;
        int u = c / 3, gg = c - u * 3;
        float v = a.Wh[(size_t)d * G3 + gg * 512 + u0 + u];
        __nv_bfloat16 hi = __float2bfloat16(v);
        __nv_bfloat16 lo = __float2bfloat16(v - __bfloat162float(hi));
        int off = ((d >> 3) * 3 + (c >> 3)) * 64 + (d & 7) * 8 + (c & 7);
        WhHi[off] = hi;
        WhLo[off] = lo;
    }
    if (tid < 24) {
        int u = tid / 3, gg = tid - u * 3;
        bhs[tid] = a.bh[gg * 512 + u0 + u];
    }
    for (int i = tid; i < 64 * 8; i += 256) hloc[i] = 0.f;

    const int kh = warp >> 2;      // K half (0/1)
    const int mt = warp & 3;       // mtile (rows mt*16..+15)
    const int g  = lane >> 3, r = lane & 7;
    const int g01 = (lane >> 3) & 1;

    const int rowI = tid >> 3;     // gate item 0 row (0..31)
    const int uI   = tid & 7;

    for (int s = 0; s < TT; s++) {
        // XW prefetch into registers (flies during staging + mma)
        float xw0r, xw0z, xw0n, xw1r, xw1z, xw1n;
        {
            const float* base = a.XW + (size_t)s * 64 * G3 + u0 + uI;
            const float* p0 = base + (size_t)rowI * G3;
            const float* p1 = base + (size_t)(rowI + 32) * G3;
            xw0r = p0[0]; xw0z = p0[512]; xw0n = p0[1024];
            xw1r = p1[0]; xw1z = p1[512]; xw1n = p1[1024];
        }

        // stage h (bf16 hi/lo tiled) into smem
        if (s == 0) {
            float4 z = make_float4(0.f, 0.f, 0.f, 0.f);
            float4* d1 = (float4*)hHi;
            float4* d2 = (float4*)hLo;
            for (int i = tid; i < 4096; i += 256) { d1[i] = z; d2[i] = z; }
        } else {
            const float4* s1 = (const float4*)a.hHi;
            const float4* s2 = (const float4*)a.hLo;
            float4* d1 = (float4*)hHi;
            float4* d2 = (float4*)hLo;
            for (int i = tid; i < 4096; i += 256) { d1[i] = s1[i]; d2[i] = s2[i]; }
        }
        __syncthreads();

        // mma over this warp's K half
        float acc[3][4];
#pragma unroll
        for (int nt = 0; nt < 3; nt++)
#pragma unroll
            for (int q = 0; q < 4; q++) acc[nt][q] = 0.f;

#pragma unroll 4
        for (int kt = 0; kt < 16; kt++) {
            const int k8a = kh * 32 + kt * 2;
            // A fragments (m16 x k16), hi and lo
            uint32_t ah[4], al[4];
            {
                int m8 = mt * 2 + (g & 1);
                int k8 = k8a + (g >> 1);
                int elem = (k8 * 8 + m8) * 64 + r * 8;
                uint32_t ad = sptr(hHi + elem);
                LDSM_X4(ah[0], ah[1], ah[2], ah[3], ad);
                ad = sptr(hLo + elem);
                LDSM_X4(al[0], al[1], al[2], al[3], ad);
            }
            // B fragments: n8 tiles 0,1 via x4t; tile 2 via x2t
            uint32_t bh[6], bl[6];
            {
                int k8 = k8a + (g & 1);
                int n8 = g >> 1;
                int elem = (k8 * 3 + n8) * 64 + r * 8;
                uint32_t bd = sptr(WhHi + elem);
                LDSM_X4T(bh[0], bh[1], bh[2], bh[3], bd);
                bd = sptr(WhLo + elem);
                LDSM_X4T(bl[0], bl[1], bl[2], bl[3], bd);
                int k8c = k8a + g01;
                int elem2 = (k8c * 3 + 2) * 64 + r * 8;
                bd = sptr(WhHi + elem2);
                LDSM_X2T(bh[4], bh[5], bd);
                bd = sptr(WhLo + elem2);
                LDSM_X2T(bl[4], bl[5], bd);
            }
#pragma unroll
            for (int nt = 0; nt < 3; nt++) {
                float* c = acc[nt];
                MMA16816(c[0], c[1], c[2], c[3],
                         ah[0], ah[1], ah[2], ah[3], bh[nt * 2], bh[nt * 2 + 1]);
                MMA16816(c[0], c[1], c[2], c[3],
                         ah[0], ah[1], ah[2], ah[3], bl[nt * 2], bl[nt * 2 + 1]);
                MMA16816(c[0], c[1], c[2], c[3],
                         al[0], al[1], al[2], al[3], bh[nt * 2], bh[nt * 2 + 1]);
            }
        }

        // write partials to smem
        {
            float* pb = part + kh * 1600;
            int prow = mt * 16 + (lane >> 2);
            int pc = (lane & 3) * 2;
#pragma unroll
            for (int nt = 0; nt < 3; nt++) {
                pb[prow * 25 + nt * 8 + pc]     = acc[nt][0];
                pb[prow * 25 + nt * 8 + pc + 1] = acc[nt][1];
                pb[(prow + 8) * 25 + nt * 8 + pc]     = acc[nt][2];
                pb[(prow + 8) * 25 + nt * 8 + pc + 1] = acc[nt][3];
            }
        }
        __syncthreads();

        // gates: 2 items per thread (rows rowI and rowI+32, unit uI)
        const int oidx = a.rev ? (TT - 1 - s) : s;
        const int cb = uI * 3;
        const float bhr = bhs[cb], bhz = bhs[cb + 1], bhn = bhs[cb + 2];
#pragma unroll
        for (int q = 0; q < 2; q++) {
            int row = rowI + q * 32;
            float gr = part[row * 25 + cb]     + part[1600 + row * 25 + cb];
            float gz = part[row * 25 + cb + 1] + part[1600 + row * 25 + cb + 1];
            float gn = part[row * 25 + cb + 2] + part[1600 + row * 25 + cb + 2];
            float xr = q ? xw1r : xw0r;
            float xz = q ? xw1z : xw0z;
            float xn = q ? xw1n : xw0n;
            float rr = 1.f / (1.f + expf(-(xr + gr + bhr)));
            float zz = 1.f / (1.f + expf(-(xz + gz + bhz)));
            float nn = tanhf(xn + rr * (gn + bhn));
            float hp = hloc[row * 8 + uI];
            float hn = (1.f - zz) * nn + zz * hp;
            hloc[row * 8 + uI] = hn;
            a.OUT[((size_t)oidx * NBATCH + row) * HID + u0 + uI] = hn;
            __nv_bfloat16 hi = __float2bfloat16(hn);
            __nv_bfloat16 lo = __float2bfloat16(hn - __bfloat162float(hi));
            int off = ((u0 >> 3) * 8 + (row >> 3)) * 64 + (row & 7) * 8 + uI;
            a.hHi[off] = hi;
            a.hLo[off] = lo;
        }

        grid_barrier(a.bar_id, cpg);
    }
}

// ---------------------------------------------------------------------------
// msg / lasth
// ---------------------------------------------------------------------------
__global__ void msg_kernel(const float* __restrict__ h, float* __restrict__ msg)
{
    int idx = blockIdx.x * blockDim.x + threadIdx.x;
    if (idx >= NBATCH * HID) return;
    int n = idx >> 9, j = idx & 511;
    int b = n >> 3;
    float s = 0.f;
#pragma unroll
    for (int aa = 0; aa < AAGENT; aa++) s += h[((b << 3) + aa) * HID + j];
    msg[idx] = (s - h[n * HID + j]) * (1.f / (AAGENT - 1));
}

__global__ void lasth_kernel(const float* __restrict__ OUT, float* __restrict__ dst)
{
    int idx = blockIdx.x * blockDim.x + threadIdx.x;
    if (idx >= BBATCH * HID) return;
    int b = idx >> 9, j = idx & 511;
    dst[idx] = OUT[((size_t)(TT - 1) * NBATCH + b * AAGENT) * HID + j];
}

// ---------------------------------------------------------------------------
// launch
// ---------------------------------------------------------------------------
extern "C" void kernel_launch(void* const* d_in, const int* in_sizes, int n_in,
                              void* d_out, int out_size)
{
    const float* article = (const float*)d_in[0];
    const float* Wx_f = (const float*)d_in[2];
    const float* Wh_f = (const float*)d_in[3];
    const float* bx_f = (const float*)d_in[4];
    const float* bh_f = (const float*)d_in[5];
    const float* Wx_b = (const float*)d_in[6];
    const float* Wh_b = (const float*)d_in[7];
    const float* bx_b = (const float*)d_in[8];
    const float* bh_b = (const float*)d_in[9];
    const float* Wp   = (const float*)d_in[10];
    const float* bp   = (const float*)d_in[11];
    const float* Wm   = (const float*)d_in[12];
    const float* bm   = (const float*)d_in[13];
    const float* Wx_c = (const float*)d_in[14];
    const float* Wh_c = (const float*)d_in[15];
    const float* bx_c = (const float*)d_in[16];
    const float* bh_c = (const float*)d_in[17];

    float *XW1, *XW2, *ENCF, *ENCB, *ENC, *hsm, *msg, *msgp;
    __nv_bfloat16 *hHiA, *hLoA, *hHiB, *hLoB;
    cudaGetSymbolAddress((void**)&XW1,  g_XW1);
    cudaGetSymbolAddress((void**)&XW2,  g_XW2);
    cudaGetSymbolAddress((void**)&ENCF, g_ENCF);
    cudaGetSymbolAddress((void**)&ENCB, g_ENCB);
    cudaGetSymbolAddress((void**)&ENC,  g_ENC);
    cudaGetSymbolAddress((void**)&hsm,  g_hsm);
    cudaGetSymbolAddress((void**)&msg,  g_msg);
    cudaGetSymbolAddress((void**)&msgp, g_msgp);
    cudaGetSymbolAddress((void**)&hHiA, g_hHiA);
    cudaGetSymbolAddress((void**)&hLoA, g_hLoA);
    cudaGetSymbolAddress((void**)&hHiB, g_hHiB);
    cudaGetSymbolAddress((void**)&hLoB, g_hLoB);

    const int M = TT * NBATCH;
    cudaFuncSetAttribute((const void*)gru_tc,
                         cudaFuncAttributeMaxDynamicSharedMemorySize, S_TOTAL);

    // 1) xW precompute for both directions (backward reads time-reversed rows)
    tgemm<<<dim3(G3 / 128, M / 128), 256>>>(article, nullptr, Wx_f, bx_f, nullptr,
                                            XW1, M, DIN, G3, 0);
    tgemm<<<dim3(G3 / 128, M / 128), 256>>>(article, nullptr, Wx_b, bx_b, nullptr,
                                            XW2, M, DIN, G3, 1);

    // 2) bidirectional recurrence (two 64-CTA barrier groups, one launch)
    GruArgs af{XW1, Wh_f, bh_f, ENCF, hHiA, hLoA, 0, 0};
    GruArgs ab{XW2, Wh_b, bh_b, ENCB, hHiB, hLoB, 1, 1};
    gru_tc<<<128, 256, S_TOTAL>>>(af, ab, 64);

    // 3) projection of per-step encodings and of final hidden
    tgemm<<<dim3(HID / 128, M / 128), 256>>>(ENCF, ENCB, Wp, bp, nullptr,
                                             ENC, M, 2 * HID, HID, 0);
    tgemm<<<dim3(HID / 128, 1), 256>>>(ENCF + (size_t)(TT - 1) * NBATCH * HID, ENCB,
                                       Wp, bp, nullptr, hsm, NBATCH, 2 * HID, HID, 0);

    // 4) communication layers
    for (int l = 0; l < LLAYER; l++) {
        const float* hsrc = (l == 0) ? hsm : (ENC + (size_t)(TT - 1) * NBATCH * HID);
        msg_kernel<<<(NBATCH * HID) / 256, 256>>>(hsrc, msg);
        tgemm<<<dim3(HID / 128, 1), 256>>>(msg, nullptr, Wm + (size_t)512 * HID, bm,
                                           nullptr, msgp, NBATCH, HID, HID, 0);
        tgemm<<<dim3(HID / 128, M / 128), 256>>>(ENC, nullptr, Wm, nullptr, msgp,
                                                 XW2, M, HID, HID, 0);
        tgemm<<<dim3(G3 / 128, M / 128), 256>>>(XW2, nullptr,
                                                Wx_c + (size_t)l * HID * G3,
                                                bx_c + (size_t)l * G3, nullptr,
                                                XW1, M, HID, G3, 0);
        float* outp = (l == LLAYER - 1) ? (float*)d_out : ENC;
        GruArgs ac{XW1, Wh_c + (size_t)l * HID * G3, bh_c + (size_t)l * G3,
                   outp, hHiA, hLoA, 0, 2 + l};
        gru_tc<<<64, 256, S_TOTAL>>>(ac, ac, 64);
    }

    // 5) tail output: last hidden of first agent per batch
    lasth_kernel<<<(BBATCH * HID + 255) / 256, 256>>>(
        (const float*)d_out, (float*)d_out + (size_t)TT * NBATCH * HID);
}

// round 4
// speedup vs baseline: 1.8353x; 1.1873x over previous
#include <cuda_runtime.h>
#include <cuda_bf16.h>
#include <math.h>
#include <stdint.h>

// Problem constants
#define TT 512
#define NBATCH 64      // B*A
#define HID 512
#define DIN 512
#define G3 1536        // 3*HID
#define BBATCH 8
#define AAGENT 8
#define LLAYER 2

// ---------------------------------------------------------------------------
// Scratch (device globals; no allocations allowed)
// ---------------------------------------------------------------------------
__device__ float g_XW1[(size_t)TT * NBATCH * G3];   // 192 MB
__device__ float g_XW2[(size_t)TT * NBATCH * G3];   // 192 MB
__device__ float g_ENCF[(size_t)TT * NBATCH * HID]; // 64 MB
__device__ float g_ENCB[(size_t)TT * NBATCH * HID]; // 64 MB
__device__ float g_ENC [(size_t)TT * NBATCH * HID]; // 64 MB
__device__ float g_hsm [NBATCH * HID];
__device__ float g_msg [NBATCH * HID];
__device__ float g_msgp[NBATCH * HID];
// h in mma A-fragment layout, double-buffered, hi(64KB)+lo(64KB) per buffer.
// [group][parity][8192 uint4]
__device__ uint4 g_hfrag[2][2][8192];
__device__ unsigned g_ctr[8];

// ---------------------------------------------------------------------------
// barrier primitives (release/acquire, no full membar)
// ---------------------------------------------------------------------------
__device__ __forceinline__ unsigned ld_acq(const unsigned* p) {
    unsigned v;
    asm volatile("ld.acquire.gpu.global.u32 %0, [%1];" : "=r"(v) : "l"(p) : "memory");
    return v;
}
__device__ __forceinline__ void red_rel(unsigned* p, unsigned v) {
    asm volatile("red.release.gpu.global.add.u32 [%0], %1;" :: "l"(p), "r"(v) : "memory");
}

// ---------------------------------------------------------------------------
// mma helpers
// ---------------------------------------------------------------------------
__device__ __forceinline__ uint32_t sptr(const void* p) {
    return (uint32_t)__cvta_generic_to_shared(p);
}

#define LDSM_X4T(R0, R1, R2, R3, ADDR)                                         \
    asm volatile("ldmatrix.sync.aligned.m8n8.x4.trans.shared.b16 "             \
                 "{%0,%1,%2,%3},[%4];"                                         \
                 : "=r"(R0), "=r"(R1), "=r"(R2), "=r"(R3) : "r"(ADDR))

#define LDSM_X4(R0, R1, R2, R3, ADDR)                                          \
    asm volatile("ldmatrix.sync.aligned.m8n8.x4.shared.b16 {%0,%1,%2,%3},[%4];"\
                 : "=r"(R0), "=r"(R1), "=r"(R2), "=r"(R3) : "r"(ADDR))

#define LDSM_X2T(R0, R1, ADDR)                                                 \
    asm volatile("ldmatrix.sync.aligned.m8n8.x2.trans.shared.b16 {%0,%1},[%2];"\
                 : "=r"(R0), "=r"(R1) : "r"(ADDR))

#define MMA16816(C0, C1, C2, C3, A0, A1, A2_, A3, B0, B1)                      \
    asm volatile("mma.sync.aligned.m16n8k16.row.col.f32.bf16.bf16.f32 "        \
                 "{%0,%1,%2,%3},{%4,%5,%6,%7},{%8,%9},{%0,%1,%2,%3};"          \
                 : "+f"(C0), "+f"(C1), "+f"(C2), "+f"(C3)                      \
                 : "r"(A0), "r"(A1), "r"(A2_), "r"(A3), "r"(B0), "r"(B1))

// ---------------------------------------------------------------------------
// Tensor-core GEMM (bf16 3-term split), now with register-prefetch pipeline.
// ---------------------------------------------------------------------------
__global__ __launch_bounds__(256) void tgemm(
    const float* __restrict__ A, const float* __restrict__ A2,
    const float* __restrict__ Bm, const float* __restrict__ bias,
    const float* __restrict__ rowAdd, float* __restrict__ C,
    int M, int K, int Nc, int revT)
{
    __shared__ __nv_bfloat16 Ah[4096], Al[4096], Bh[4096], Bl[4096];

    const int tid  = threadIdx.x;
    const int lane = tid & 31;
    const int warp = tid >> 5;
    const int warpM = warp >> 2;
    const int warpN = warp & 3;
    const int row0 = blockIdx.y * 128;
    const int col0 = blockIdx.x * 128;
    const int lda = (A2 != nullptr) ? 512 : K;

    float acc[4][4][4];
#pragma unroll
    for (int mt = 0; mt < 4; mt++)
#pragma unroll
        for (int nt = 0; nt < 4; nt++)
#pragma unroll
            for (int q = 0; q < 4; q++) acc[mt][nt][q] = 0.f;

    const int g = lane >> 3, r = lane & 7;

    float2 va[8], vb[8];

    auto loadTiles = [&](int k0) {
#pragma unroll
        for (int e = 0; e < 8; e++) {
            int id = e * 256 + tid;
            int m  = id >> 4;
            int k  = (id & 15) << 1;
            float2 v = make_float2(0.f, 0.f);
            int gm = row0 + m;
            if (gm < M) {
                int kk = k0 + k;
                const float* Ap = A;
                int ka = kk;
                if (A2 != nullptr && kk >= 512) { Ap = A2; ka = kk - 512; }
                int mp = gm;
                if (revT) mp = (511 - (gm >> 6)) * 64 + (gm & 63);
                v = *(const float2*)(Ap + (size_t)mp * lda + ka);
            }
            va[e] = v;
        }
#pragma unroll
        for (int e = 0; e < 8; e++) {
            int id = e * 256 + tid;
            int k  = id >> 6;
            int n  = (id & 63) << 1;
            vb[e] = *(const float2*)(Bm + (size_t)(k0 + k) * Nc + col0 + n);
        }
    };

    auto storeTiles = [&]() {
#pragma unroll
        for (int e = 0; e < 8; e++) {
            int id = e * 256 + tid;
            int m  = id >> 4;
            int k  = (id & 15) << 1;
            float2 v = va[e];
            __nv_bfloat16 h0 = __float2bfloat16(v.x);
            __nv_bfloat16 h1 = __float2bfloat16(v.y);
            __nv_bfloat16 l0 = __float2bfloat16(v.x - __bfloat162float(h0));
            __nv_bfloat16 l1 = __float2bfloat16(v.y - __bfloat162float(h1));
            int off = (((k >> 3) << 4) + (m >> 3)) * 64 + ((m & 7) << 3) + (k & 7);
            __nv_bfloat162 ph; ph.x = h0; ph.y = h1;
            __nv_bfloat162 pl; pl.x = l0; pl.y = l1;
            *(__nv_bfloat162*)(Ah + off) = ph;
            *(__nv_bfloat162*)(Al + off) = pl;
        }
#pragma unroll
        for (int e = 0; e < 8; e++) {
            int id = e * 256 + tid;
            int k  = id >> 6;
            int n  = (id & 63) << 1;
            float2 v = vb[e];
            __nv_bfloat16 h0 = __float2bfloat16(v.x);
            __nv_bfloat16 h1 = __float2bfloat16(v.y);
            __nv_bfloat16 l0 = __float2bfloat16(v.x - __bfloat162float(h0));
            __nv_bfloat16 l1 = __float2bfloat16(v.y - __bfloat162float(h1));
            int off = (((k >> 3) << 4) + (n >> 3)) * 64 + ((k & 7) << 3) + (n & 7);
            __nv_bfloat162 ph; ph.x = h0; ph.y = h1;
            __nv_bfloat162 pl; pl.x = l0; pl.y = l1;
            *(__nv_bfloat162*)(Bh + off) = ph;
            *(__nv_bfloat162*)(Bl + off) = pl;
        }
    };

    loadTiles(0);

    for (int k0 = 0; k0 < K; k0 += 32) {
        storeTiles();
        __syncthreads();
        if (k0 + 32 < K) loadTiles(k0 + 32);   // overlap with mma below

#pragma unroll
        for (int kc = 0; kc < 2; kc++) {
            uint32_t bh[8], bl[8];
#pragma unroll
            for (int np = 0; np < 2; np++) {
                int k8 = kc * 2 + (g & 1);
                int n8 = warpN * 4 + np * 2 + (g >> 1);
                int elem = (k8 * 16 + n8) * 64 + r * 8;
                uint32_t ad = sptr(Bh + elem);
                LDSM_X4T(bh[np * 4 + 0], bh[np * 4 + 1],
                         bh[np * 4 + 2], bh[np * 4 + 3], ad);
                ad = sptr(Bl + elem);
                LDSM_X4T(bl[np * 4 + 0], bl[np * 4 + 1],
                         bl[np * 4 + 2], bl[np * 4 + 3], ad);
            }
#pragma unroll
            for (int mt = 0; mt < 4; mt++) {
                int m8 = warpM * 8 + mt * 2 + (g & 1);
                int k8 = kc * 2 + (g >> 1);
                int elem = (k8 * 16 + m8) * 64 + r * 8;
                uint32_t ah[4], al[4];
                uint32_t ad = sptr(Ah + elem);
                LDSM_X4(ah[0], ah[1], ah[2], ah[3], ad);
                ad = sptr(Al + elem);
                LDSM_X4(al[0], al[1], al[2], al[3], ad);
#pragma unroll
                for (int nt = 0; nt < 4; nt++) {
                    float* c = acc[mt][nt];
                    MMA16816(c[0], c[1], c[2], c[3],
                             ah[0], ah[1], ah[2], ah[3], bh[nt * 2], bh[nt * 2 + 1]);
                    MMA16816(c[0], c[1], c[2], c[3],
                             ah[0], ah[1], ah[2], ah[3], bl[nt * 2], bl[nt * 2 + 1]);
                    MMA16816(c[0], c[1], c[2], c[3],
                             al[0], al[1], al[2], al[3], bh[nt * 2], bh[nt * 2 + 1]);
                }
            }
        }
        __syncthreads();
    }

#pragma unroll
    for (int mt = 0; mt < 4; mt++) {
#pragma unroll
        for (int nt = 0; nt < 4; nt++) {
            int rA = row0 + warpM * 64 + mt * 16 + (lane >> 2);
            int cg = col0 + warpN * 32 + nt * 8 + ((lane & 3) << 1);
            float b0 = 0.f, b1 = 0.f;
            if (bias) { b0 = bias[cg]; b1 = bias[cg + 1]; }
#pragma unroll
            for (int half = 0; half < 2; half++) {
                int m = rA + half * 8;
                if (m >= M) continue;
                float v0 = acc[mt][nt][half * 2 + 0] + b0;
                float v1 = acc[mt][nt][half * 2 + 1] + b1;
                if (rowAdd) {
                    int rm = (m & 63) * Nc;
                    v0 += rowAdd[rm + cg];
                    v1 += rowAdd[rm + cg + 1];
                }
                float2 o; o.x = v0; o.y = v1;
                *(float2*)(C + (size_t)m * Nc + cg) = o;
            }
        }
    }
}

// ---------------------------------------------------------------------------
// Tensor-core persistent GRU scan, direct-LDG fragment-layout h.
//   h circulates in g_hfrag (mma A-fragment layout, bf16 hi/lo, double-
//   buffered). Producers scatter 2-byte values; consumers LDG.128 straight
//   into mma operands. Light release/acquire barrier per step.
// ---------------------------------------------------------------------------
struct GruArgs {
    const float* XW;        // [T, 64, 1536]
    const float* Wh;        // [512, 1536]
    const float* bh;        // [1536]
    float* OUT;             // [T, 64, 512]
    uint4* hb0;             // parity-0 fragment buffer (8192 uint4)
    uint4* hb1;             // parity-1
    int rev;
    int bar_id;
};

// smem byte offsets
#define S_WHHI 0
#define S_WHLO 24576
#define S_PART 49152
#define S_BHS  61952
#define S_TOTAL 62080

__global__ __launch_bounds__(256) void gru_tc(GruArgs a0, GruArgs a1, int cpg)
{
    extern __shared__ char smraw[];
    __nv_bfloat16* WhHi = (__nv_bfloat16*)(smraw + S_WHHI);
    __nv_bfloat16* WhLo = (__nv_bfloat16*)(smraw + S_WHLO);
    float* part = (float*)(smraw + S_PART);   // [2][64*25]
    float* bhs  = (float*)(smraw + S_BHS);    // [24]

    const int tid  = threadIdx.x;
    const int lane = tid & 31;
    const int warp = tid >> 5;
    const GruArgs a = (blockIdx.x / cpg == 0) ? a0 : a1;
    const int bl = blockIdx.x % cpg;
    const int u0 = bl * 8;

    // one-time: Wh slice -> smem bf16 hi/lo (ldmatrix-tiled, 3 n8 blocks)
    for (int idx = tid; idx < 512 * 24; idx += 256) {
        int d = idx / 24, c = idx - d * 24;
        int u = c / 3, gg = c - u * 3;
        float v = a.Wh[(size_t)d * G3 + gg * 512 + u0 + u];
        __nv_bfloat16 hi = __float2bfloat16(v);
        __nv_bfloat16 lo = __float2bfloat16(v - __bfloat162float(hi));
        int off = ((d >> 3) * 3 + (c >> 3)) * 64 + (d & 7) * 8 + (c & 7);
        WhHi[off] = hi;
        WhLo[off] = lo;
    }
    if (tid < 24) {
        int u = tid / 3, gg = tid - u * 3;
        bhs[tid] = a.bh[gg * 512 + u0 + u];
    }
    // zero my slice of the parity-1 buffer (h_{-1} = 0)
    {
        int zn = 8192 / cpg;
        uint4 z; z.x = z.y = z.z = z.w = 0u;
        for (int i = tid; i < zn; i += 256) a.hb1[bl * zn + i] = z;
    }
    __syncthreads();
    unsigned* ctr = &g_ctr[a.bar_id];
    if (tid == 0) red_rel(ctr, 1);

    // per-thread constants
    const int kh = warp >> 2;      // K half (0/1)
    const int mt = warp & 3;       // mtile (rows mt*16..+15)
    const int g  = lane >> 3, r = lane & 7;
    const int g01 = g & 1;
    const int rowI = tid >> 3;     // gate item 0 row (0..31)
    const int uI   = tid & 7;
    const int cb   = uI * 3;
    const float bhr = bhs[cb], bhz = bhs[cb + 1], bhn = bhs[cb + 2];

    // producer scatter offsets (byte) for q=0,1
    int oQ[2];
    {
        int u = u0 + uI;
        int khp = u >> 8, ktp = (u >> 4) & 15, k_in = u & 15;
#pragma unroll
        for (int q = 0; q < 2; q++) {
            int row = rowI + q * 32;
            int mtp = row >> 4, m_in = row & 15;
            int lanep = (m_in & 7) * 4 + ((k_in & 7) >> 1);
            int regp = ((m_in >> 3) & 1) + (((k_in >> 3) & 1) << 1);
            oQ[q] = ((((khp * 16 + ktp) * 4 + mtp) * 32 + lanep) << 4)
                    + regp * 4 + (k_in & 1) * 2;
        }
    }
    float hp0 = 0.f, hp1 = 0.f;

    for (int s = 0; s < TT; s++) {
        // XW prefetch (independent of barrier; hides DRAM latency under wait)
        float xw0r, xw0z, xw0n, xw1r, xw1z, xw1n;
        {
            const float* p0 = a.XW + ((size_t)s * 64 + rowI) * G3 + u0 + uI;
            const float* p1 = p0 + (size_t)32 * G3;
            xw0r = p0[0]; xw0z = p0[512]; xw0n = p0[1024];
            xw1r = p1[0]; xw1z = p1[512]; xw1n = p1[1024];
        }

        // wait for all h_{s-1}
        if (tid == 0) {
            unsigned target = (unsigned)(s + 1) * (unsigned)cpg;
            while (ld_acq(ctr) < target) { }
        }
        __syncthreads();

        // mma: A-frags straight from global fragment buffer
        const uint4* rb = (s & 1) ? a.hb0 : a.hb1;
        float acc[3][4];
#pragma unroll
        for (int nt = 0; nt < 3; nt++)
#pragma unroll
            for (int q = 0; q < 4; q++) acc[nt][q] = 0.f;

#pragma unroll 4
        for (int kt = 0; kt < 16; kt++) {
            int idx = ((kh * 16 + kt) * 4 + mt) * 32 + lane;
            uint4 AH = rb[idx];
            uint4 AL = rb[idx + 4096];

            const int k8a = kh * 32 + kt * 2;
            uint32_t bh6[6], bl6[6];
            {
                int k8 = k8a + (g & 1);
                int n8 = g >> 1;
                int elem = (k8 * 3 + n8) * 64 + r * 8;
                uint32_t bd = sptr(WhHi + elem);
                LDSM_X4T(bh6[0], bh6[1], bh6[2], bh6[3], bd);
                bd = sptr(WhLo + elem);
                LDSM_X4T(bl6[0], bl6[1], bl6[2], bl6[3], bd);
                int k8c = k8a + g01;
                int elem2 = (k8c * 3 + 2) * 64 + r * 8;
                bd = sptr(WhHi + elem2);
                LDSM_X2T(bh6[4], bh6[5], bd);
                bd = sptr(WhLo + elem2);
                LDSM_X2T(bl6[4], bl6[5], bd);
            }
#pragma unroll
            for (int nt = 0; nt < 3; nt++) {
                float* c = acc[nt];
                MMA16816(c[0], c[1], c[2], c[3],
                         AH.x, AH.y, AH.z, AH.w, bh6[nt * 2], bh6[nt * 2 + 1]);
                MMA16816(c[0], c[1], c[2], c[3],
                         AH.x, AH.y, AH.z, AH.w, bl6[nt * 2], bl6[nt * 2 + 1]);
                MMA16816(c[0], c[1], c[2], c[3],
                         AL.x, AL.y, AL.z, AL.w, bh6[nt * 2], bh6[nt * 2 + 1]);
            }
        }

        // write partials to smem
        {
            float* pb = part + kh * 1600;
            int prow = mt * 16 + (lane >> 2);
            int pc = (lane & 3) * 2;
#pragma unroll
            for (int nt = 0; nt < 3; nt++) {
                pb[prow * 25 + nt * 8 + pc]     = acc[nt][0];
                pb[prow * 25 + nt * 8 + pc + 1] = acc[nt][1];
                pb[(prow + 8) * 25 + nt * 8 + pc]     = acc[nt][2];
                pb[(prow + 8) * 25 + nt * 8 + pc + 1] = acc[nt][3];
            }
        }
        __syncthreads();

        // gates: 2 items per thread (rows rowI, rowI+32; unit uI)
        const int oidx = a.rev ? (TT - 1 - s) : s;
        char* wb = (char*)((s & 1) ? a.hb1 : a.hb0);
#pragma unroll
        for (int q = 0; q < 2; q++) {
            int row = rowI + q * 32;
            float gr = part[row * 25 + cb]     + part[1600 + row * 25 + cb];
            float gz = part[row * 25 + cb + 1] + part[1600 + row * 25 + cb + 1];
            float gn = part[row * 25 + cb + 2] + part[1600 + row * 25 + cb + 2];
            float xr = q ? xw1r : xw0r;
            float xz = q ? xw1z : xw0z;
            float xn = q ? xw1n : xw0n;
            float rr = 1.f / (1.f + expf(-(xr + gr + bhr)));
            float zz = 1.f / (1.f + expf(-(xz + gz + bhz)));
            float nn = tanhf(xn + rr * (gn + bhn));
            float hp = q ? hp1 : hp0;
            float hn = (1.f - zz) * nn + zz * hp;
            if (q) hp1 = hn; else hp0 = hn;
            a.OUT[((size_t)oidx * NBATCH + row) * HID + u0 + uI] = hn;
            __nv_bfloat16 hi = __float2bfloat16(hn);
            __nv_bfloat16 lo = __float2bfloat16(hn - __bfloat162float(hi));
            *(__nv_bfloat16*)(wb + oQ[q]) = hi;
            *(__nv_bfloat16*)(wb + 65536 + oQ[q]) = lo;
        }
        __syncthreads();
        if (tid == 0) red_rel(ctr, 1);
    }

    // reset counter for graph replay determinism
    if (bl == 0 && tid == 0) {
        unsigned fin = 513u * (unsigned)cpg;
        while (ld_acq(ctr) < fin) { }
        asm volatile("st.global.relaxed.gpu.u32 [%0], %1;" :: "l"(ctr), "r"(0u));
    }
}

// ---------------------------------------------------------------------------
// msg / lasth
// ---------------------------------------------------------------------------
__global__ void msg_kernel(const float* __restrict__ h, float* __restrict__ msg)
{
    int idx = blockIdx.x * blockDim.x + threadIdx.x;
    if (idx >= NBATCH * HID) return;
    int n = idx >> 9, j = idx & 511;
    int b = n >> 3;
    float s = 0.f;
#pragma unroll
    for (int aa = 0; aa < AAGENT; aa++) s += h[((b << 3) + aa) * HID + j];
    msg[idx] = (s - h[n * HID + j]) * (1.f / (AAGENT - 1));
}

__global__ void lasth_kernel(const float* __restrict__ OUT, float* __restrict__ dst)
{
    int idx = blockIdx.x * blockDim.x + threadIdx.x;
    if (idx >= BBATCH * HID) return;
    int b = idx >> 9, j = idx & 511;
    dst[idx] = OUT[((size_t)(TT - 1) * NBATCH + b * AAGENT) * HID + j];
}

// ---------------------------------------------------------------------------
// launch
// ---------------------------------------------------------------------------
extern "C" void kernel_launch(void* const* d_in, const int* in_sizes, int n_in,
                              void* d_out, int out_size)
{
    const float* article = (const float*)d_in[0];
    const float* Wx_f = (const float*)d_in[2];
    const float* Wh_f = (const float*)d_in[3];
    const float* bx_f = (const float*)d_in[4];
    const float* bh_f = (const float*)d_in[5];
    const float* Wx_b = (const float*)d_in[6];
    const float* Wh_b = (const float*)d_in[7];
    const float* bx_b = (const float*)d_in[8];
    const float* bh_b = (const float*)d_in[9];
    const float* Wp   = (const float*)d_in[10];
    const float* bp   = (const float*)d_in[11];
    const float* Wm   = (const float*)d_in[12];
    const float* bm   = (const float*)d_in[13];
    const float* Wx_c = (const float*)d_in[14];
    const float* Wh_c = (const float*)d_in[15];
    const float* bx_c = (const float*)d_in[16];
    const float* bh_c = (const float*)d_in[17];

    float *XW1, *XW2, *ENCF, *ENCB, *ENC, *hsm, *msg, *msgp;
    uint4* hfrag;
    cudaGetSymbolAddress((void**)&XW1,  g_XW1);
    cudaGetSymbolAddress((void**)&XW2,  g_XW2);
    cudaGetSymbolAddress((void**)&ENCF, g_ENCF);
    cudaGetSymbolAddress((void**)&ENCB, g_ENCB);
    cudaGetSymbolAddress((void**)&ENC,  g_ENC);
    cudaGetSymbolAddress((void**)&hsm,  g_hsm);
    cudaGetSymbolAddress((void**)&msg,  g_msg);
    cudaGetSymbolAddress((void**)&msgp, g_msgp);
    cudaGetSymbolAddress((void**)&hfrag, g_hfrag);
    uint4* hA0 = hfrag;
    uint4* hA1 = hfrag + 8192;
    uint4* hB0 = hfrag + 16384;
    uint4* hB1 = hfrag + 24576;

    const int M = TT * NBATCH;
    cudaFuncSetAttribute((const void*)gru_tc,
                         cudaFuncAttributeMaxDynamicSharedMemorySize, S_TOTAL);

    // 1) xW precompute for both directions (backward reads time-reversed rows)
    tgemm<<<dim3(G3 / 128, M / 128), 256>>>(article, nullptr, Wx_f, bx_f, nullptr,
                                            XW1, M, DIN, G3, 0);
    tgemm<<<dim3(G3 / 128, M / 128), 256>>>(article, nullptr, Wx_b, bx_b, nullptr,
                                            XW2, M, DIN, G3, 1);

    // 2) bidirectional recurrence (two 64-CTA barrier groups, one launch)
    GruArgs af{XW1, Wh_f, bh_f, ENCF, hA0, hA1, 0, 0};
    GruArgs ab{XW2, Wh_b, bh_b, ENCB, hB0, hB1, 1, 1};
    gru_tc<<<128, 256, S_TOTAL>>>(af, ab, 64);

    // 3) projection of per-step encodings and of final hidden
    tgemm<<<dim3(HID / 128, M / 128), 256>>>(ENCF, ENCB, Wp, bp, nullptr,
                                             ENC, M, 2 * HID, HID, 0);
    tgemm<<<dim3(HID / 128, 1), 256>>>(ENCF + (size_t)(TT - 1) * NBATCH * HID, ENCB,
                                       Wp, bp, nullptr, hsm, NBATCH, 2 * HID, HID, 0);

    // 4) communication layers
    for (int l = 0; l < LLAYER; l++) {
        const float* hsrc = (l == 0) ? hsm : (ENC + (size_t)(TT - 1) * NBATCH * HID);
        msg_kernel<<<(NBATCH * HID) / 256, 256>>>(hsrc, msg);
        tgemm<<<dim3(HID / 128, 1), 256>>>(msg, nullptr, Wm + (size_t)512 * HID, bm,
                                           nullptr, msgp, NBATCH, HID, HID, 0);
        tgemm<<<dim3(HID / 128, M / 128), 256>>>(ENC, nullptr, Wm, nullptr, msgp,
                                                 XW2, M, HID, HID, 0);
        tgemm<<<dim3(G3 / 128, M / 128), 256>>>(XW2, nullptr,
                                                Wx_c + (size_t)l * HID * G3,
                                                bx_c + (size_t)l * G3, nullptr,
                                                XW1, M, HID, G3, 0);
        float* outp = (l == LLAYER - 1) ? (float*)d_out : ENC;
        GruArgs ac{XW1, Wh_c + (size_t)l * HID * G3, bh_c + (size_t)l * G3,
                   outp, hA0, hA1, 0, 2 + l};
        gru_tc<<<64, 256, S_TOTAL>>>(ac, ac, 64);
    }

    // 5) tail output: last hidden of first agent per batch
    lasth_kernel<<<(BBATCH * HID + 255) / 256, 256>>>(
        (const float*)d_out, (float*)d_out + (size_t)TT * NBATCH * HID);
}

// round 5
// speedup vs baseline: 2.4325x; 1.3254x over previous
#include <cuda_runtime.h>
#include <cuda_bf16.h>
#include <math.h>
#include <stdint.h>

// Problem constants
#define TT 512
#define NBATCH 64      // B*A
#define HID 512
#define DIN 512
#define G3 1536        // 3*HID
#define BBATCH 8
#define AAGENT 8
#define LLAYER 2

// ---------------------------------------------------------------------------
// Scratch (device globals; no allocations allowed)
// ---------------------------------------------------------------------------
__device__ float g_XW1[(size_t)TT * NBATCH * G3];   // 192 MB
__device__ float g_XW2[(size_t)TT * NBATCH * G3];   // 192 MB
__device__ float g_ENCF[(size_t)TT * NBATCH * HID]; // 64 MB
__device__ float g_ENCB[(size_t)TT * NBATCH * HID]; // 64 MB
__device__ float g_ENC [(size_t)TT * NBATCH * HID]; // 64 MB
__device__ float g_hsm [NBATCH * HID];
__device__ float g_msg [NBATCH * HID];
__device__ float g_msgp[NBATCH * HID];
// h in mma A-fragment layout, double-buffered, hi(64KB)+lo(64KB) per buffer.
__device__ uint4 g_hfrag[2][2][8192];
// distributed barrier flags: 4 groups x 64 CTAs x 128B slots
#define FSTR 32
__device__ unsigned g_flags[4][64 * FSTR];

// ---------------------------------------------------------------------------
// barrier primitives
// ---------------------------------------------------------------------------
__device__ __forceinline__ unsigned ld_acq(const unsigned* p) {
    unsigned v;
    asm volatile("ld.acquire.gpu.global.u32 %0, [%1];" : "=r"(v) : "l"(p) : "memory");
    return v;
}
__device__ __forceinline__ void st_rel(unsigned* p, unsigned v) {
    asm volatile("st.release.gpu.global.u32 [%0], %1;" :: "l"(p), "r"(v) : "memory");
}

// ---------------------------------------------------------------------------
// mma helpers
// ---------------------------------------------------------------------------
__device__ __forceinline__ uint32_t sptr(const void* p) {
    return (uint32_t)__cvta_generic_to_shared(p);
}

#define LDSM_X4T(R0, R1, R2, R3, ADDR)                                         \
    asm volatile("ldmatrix.sync.aligned.m8n8.x4.trans.shared.b16 "             \
                 "{%0,%1,%2,%3},[%4];"                                         \
                 : "=r"(R0), "=r"(R1), "=r"(R2), "=r"(R3) : "r"(ADDR))

#define LDSM_X4(R0, R1, R2, R3, ADDR)                                          \
    asm volatile("ldmatrix.sync.aligned.m8n8.x4.shared.b16 {%0,%1,%2,%3},[%4];"\
                 : "=r"(R0), "=r"(R1), "=r"(R2), "=r"(R3) : "r"(ADDR))

#define LDSM_X2T(R0, R1, ADDR)                                                 \
    asm volatile("ldmatrix.sync.aligned.m8n8.x2.trans.shared.b16 {%0,%1},[%2];"\
                 : "=r"(R0), "=r"(R1) : "r"(ADDR))

#define MMA16816(C0, C1, C2, C3, A0, A1, A2_, A3, B0, B1)                      \
    asm volatile("mma.sync.aligned.m16n8k16.row.col.f32.bf16.bf16.f32 "        \
                 "{%0,%1,%2,%3},{%4,%5,%6,%7},{%8,%9},{%0,%1,%2,%3};"          \
                 : "+f"(C0), "+f"(C1), "+f"(C2), "+f"(C3)                      \
                 : "r"(A0), "r"(A1), "r"(A2_), "r"(A3), "r"(B0), "r"(B1))

// ---------------------------------------------------------------------------
// Tensor-core GEMM (bf16 3-term split), register-prefetch pipeline.
// ---------------------------------------------------------------------------
__global__ __launch_bounds__(256) void tgemm(
    const float* __restrict__ A, const float* __restrict__ A2,
    const float* __restrict__ Bm, const float* __restrict__ bias,
    const float* __restrict__ rowAdd, float* __restrict__ C,
    int M, int K, int Nc, int revT)
{
    __shared__ __nv_bfloat16 Ah[4096], Al[4096], Bh[4096], Bl[4096];

    const int tid  = threadIdx.x;
    const int lane = tid & 31;
    const int warp = tid >> 5;
    const int warpM = warp >> 2;
    const int warpN = warp & 3;
    const int row0 = blockIdx.y * 128;
    const int col0 = blockIdx.x * 128;
    const int lda = (A2 != nullptr) ? 512 : K;

    float acc[4][4][4];
#pragma unroll
    for (int mt = 0; mt < 4; mt++)
#pragma unroll
        for (int nt = 0; nt < 4; nt++)
#pragma unroll
            for (int q = 0; q < 4; q++) acc[mt][nt][q] = 0.f;

    const int g = lane >> 3, r = lane & 7;

    float2 va[8], vb[8];

    auto loadTiles = [&](int k0) {
#pragma unroll
        for (int e = 0; e < 8; e++) {
            int id = e * 256 + tid;
            int m  = id >> 4;
            int k  = (id & 15) << 1;
            float2 v = make_float2(0.f, 0.f);
            int gm = row0 + m;
            if (gm < M) {
                int kk = k0 + k;
                const float* Ap = A;
                int ka = kk;
                if (A2 != nullptr && kk >= 512) { Ap = A2; ka = kk - 512; }
                int mp = gm;
                if (revT) mp = (511 - (gm >> 6)) * 64 + (gm & 63);
                v = *(const float2*)(Ap + (size_t)mp * lda + ka);
            }
            va[e] = v;
        }
#pragma unroll
        for (int e = 0; e < 8; e++) {
            int id = e * 256 + tid;
            int k  = id >> 6;
            int n  = (id & 63) << 1;
            vb[e] = *(const float2*)(Bm + (size_t)(k0 + k) * Nc + col0 + n);
        }
    };

    auto storeTiles = [&]() {
#pragma unroll
        for (int e = 0; e < 8; e++) {
            int id = e * 256 + tid;
            int m  = id >> 4;
            int k  = (id & 15) << 1;
            float2 v = va[e];
            __nv_bfloat16 h0 = __float2bfloat16(v.x);
            __nv_bfloat16 h1 = __float2bfloat16(v.y);
            __nv_bfloat16 l0 = __float2bfloat16(v.x - __bfloat162float(h0));
            __nv_bfloat16 l1 = __float2bfloat16(v.y - __bfloat162float(h1));
            int off = (((k >> 3) << 4) + (m >> 3)) * 64 + ((m & 7) << 3) + (k & 7);
            __nv_bfloat162 ph; ph.x = h0; ph.y = h1;
            __nv_bfloat162 pl; pl.x = l0; pl.y = l1;
            *(__nv_bfloat162*)(Ah + off) = ph;
            *(__nv_bfloat162*)(Al + off) = pl;
        }
#pragma unroll
        for (int e = 0; e < 8; e++) {
            int id = e * 256 + tid;
            int k  = id >> 6;
            int n  = (id & 63) << 1;
            float2 v = vb[e];
            __nv_bfloat16 h0 = __float2bfloat16(v.x);
            __nv_bfloat16 h1 = __float2bfloat16(v.y);
            __nv_bfloat16 l0 = __float2bfloat16(v.x - __bfloat162float(h0));
            __nv_bfloat16 l1 = __float2bfloat16(v.y - __bfloat162float(h1));
            int off = (((k >> 3) << 4) + (n >> 3)) * 64 + ((k & 7) << 3) + (n & 7);
            __nv_bfloat162 ph; ph.x = h0; ph.y = h1;
            __nv_bfloat162 pl; pl.x = l0; pl.y = l1;
            *(__nv_bfloat162*)(Bh + off) = ph;
            *(__nv_bfloat162*)(Bl + off) = pl;
        }
    };

    loadTiles(0);

    for (int k0 = 0; k0 < K; k0 += 32) {
        storeTiles();
        __syncthreads();
        if (k0 + 32 < K) loadTiles(k0 + 32);   // overlap with mma below

#pragma unroll
        for (int kc = 0; kc < 2; kc++) {
            uint32_t bh[8], bl[8];
#pragma unroll
            for (int np = 0; np < 2; np++) {
                int k8 = kc * 2 + (g & 1);
                int n8 = warpN * 4 + np * 2 + (g >> 1);
                int elem = (k8 * 16 + n8) * 64 + r * 8;
                uint32_t ad = sptr(Bh + elem);
                LDSM_X4T(bh[np * 4 + 0], bh[np * 4 + 1],
                         bh[np * 4 + 2], bh[np * 4 + 3], ad);
                ad = sptr(Bl + elem);
                LDSM_X4T(bl[np * 4 + 0], bl[np * 4 + 1],
                         bl[np * 4 + 2], bl[np * 4 + 3], ad);
            }
#pragma unroll
            for (int mt = 0; mt < 4; mt++) {
                int m8 = warpM * 8 + mt * 2 + (g & 1);
                int k8 = kc * 2 + (g >> 1);
                int elem = (k8 * 16 + m8) * 64 + r * 8;
                uint32_t ah[4], al[4];
                uint32_t ad = sptr(Ah + elem);
                LDSM_X4(ah[0], ah[1], ah[2], ah[3], ad);
                ad = sptr(Al + elem);
                LDSM_X4(al[0], al[1], al[2], al[3], ad);
#pragma unroll
                for (int nt = 0; nt < 4; nt++) {
                    float* c = acc[mt][nt];
                    MMA16816(c[0], c[1], c[2], c[3],
                             ah[0], ah[1], ah[2], ah[3], bh[nt * 2], bh[nt * 2 + 1]);
                    MMA16816(c[0], c[1], c[2], c[3],
                             ah[0], ah[1], ah[2], ah[3], bl[nt * 2], bl[nt * 2 + 1]);
                    MMA16816(c[0], c[1], c[2], c[3],
                             al[0], al[1], al[2], al[3], bh[nt * 2], bh[nt * 2 + 1]);
                }
            }
        }
        __syncthreads();
    }

#pragma unroll
    for (int mt = 0; mt < 4; mt++) {
#pragma unroll
        for (int nt = 0; nt < 4; nt++) {
            int rA = row0 + warpM * 64 + mt * 16 + (lane >> 2);
            int cg = col0 + warpN * 32 + nt * 8 + ((lane & 3) << 1);
            float b0 = 0.f, b1 = 0.f;
            if (bias) { b0 = bias[cg]; b1 = bias[cg + 1]; }
#pragma unroll
            for (int half = 0; half < 2; half++) {
                int m = rA + half * 8;
                if (m >= M) continue;
                float v0 = acc[mt][nt][half * 2 + 0] + b0;
                float v1 = acc[mt][nt][half * 2 + 1] + b1;
                if (rowAdd) {
                    int rm = (m & 63) * Nc;
                    v0 += rowAdd[rm + cg];
                    v1 += rowAdd[rm + cg + 1];
                }
                float2 o; o.x = v0; o.y = v1;
                *(float2*)(C + (size_t)m * Nc + cg) = o;
            }
        }
    }
}

// ---------------------------------------------------------------------------
// Tensor-core persistent GRU scan, direct-LDG fragment h + distributed-flag
// barrier (per-CTA 128B slots; arrive = one st.release; wait = parallel
// acquire-poll of all 64 slots by warp 0).
// ---------------------------------------------------------------------------
struct GruArgs {
    const float* XW;        // [T, 64, 1536]
    const float* Wh;        // [512, 1536]
    const float* bh;        // [1536]
    float* OUT;             // [T, 64, 512]
    uint4* hb0;             // parity-0 fragment buffer (8192 uint4)
    uint4* hb1;             // parity-1
    unsigned* flags;        // [64 * FSTR]
    int rev;
};

// smem byte offsets
#define S_WHHI 0
#define S_WHLO 24576
#define S_PART 49152
#define S_BHS  61952
#define S_TOTAL 62080

__global__ __launch_bounds__(256, 1) void gru_tc(GruArgs a0, GruArgs a1, int cpg)
{
    extern __shared__ char smraw[];
    __nv_bfloat16* WhHi = (__nv_bfloat16*)(smraw + S_WHHI);
    __nv_bfloat16* WhLo = (__nv_bfloat16*)(smraw + S_WHLO);
    float* part = (float*)(smraw + S_PART);   // [2][64*25]
    float* bhs  = (float*)(smraw + S_BHS);    // [24]

    const int tid  = threadIdx.x;
    const int lane = tid & 31;
    const int warp = tid >> 5;
    const GruArgs a = (blockIdx.x / cpg == 0) ? a0 : a1;
    const int bl = blockIdx.x % cpg;
    const int u0 = bl * 8;

    // one-time: Wh slice -> smem bf16 hi/lo (ldmatrix-tiled, 3 n8 blocks)
    for (int idx = tid; idx < 512 * 24; idx += 256) {
        int d = idx / 24, c = idx - d * 24;
        int u = c / 3, gg = c - u * 3;
        float v = a.Wh[(size_t)d * G3 + gg * 512 + u0 + u];
        __nv_bfloat16 hi = __float2bfloat16(v);
        __nv_bfloat16 lo = __float2bfloat16(v - __bfloat162float(hi));
        int off = ((d >> 3) * 3 + (c >> 3)) * 64 + (d & 7) * 8 + (c & 7);
        WhHi[off] = hi;
        WhLo[off] = lo;
    }
    if (tid < 24) {
        int u = tid / 3, gg = tid - u * 3;
        bhs[tid] = a.bh[gg * 512 + u0 + u];
    }
    // zero my slice of the parity-1 buffer (h_{-1} = 0)
    {
        int zn = 8192 / cpg;
        uint4 z; z.x = z.y = z.z = z.w = 0u;
        for (int i = tid; i < zn; i += 256) a.hb1[bl * zn + i] = z;
    }
    __syncthreads();
    if (tid == 0) st_rel(&a.flags[bl * FSTR], 1u);

    // per-thread constants
    const int kh = warp >> 2;      // K half (0/1)
    const int mt = warp & 3;       // mtile (rows mt*16..+15)
    const int g  = lane >> 3, r = lane & 7;
    const int g01 = g & 1;
    const int rowI = tid >> 3;     // gate item 0 row (0..31)
    const int uI   = tid & 7;
    const int cb   = uI * 3;
    const float bhr = bhs[cb], bhz = bhs[cb + 1], bhn = bhs[cb + 2];

    // poll addresses for warp 0 (2 slots per lane)
    const unsigned* fp0 = a.flags + (2 * lane) * FSTR;
    const unsigned* fp1 = a.flags + (2 * lane + 1) * FSTR;

    // producer scatter offsets (byte) for q=0,1
    int oQ[2];
    {
        int u = u0 + uI;
        int khp = u >> 8, ktp = (u >> 4) & 15, k_in = u & 15;
#pragma unroll
        for (int q = 0; q < 2; q++) {
            int row = rowI + q * 32;
            int mtp = row >> 4, m_in = row & 15;
            int lanep = (m_in & 7) * 4 + ((k_in & 7) >> 1);
            int regp = ((m_in >> 3) & 1) + (((k_in >> 3) & 1) << 1);
            oQ[q] = ((((khp * 16 + ktp) * 4 + mtp) * 32 + lanep) << 4)
                    + regp * 4 + (k_in & 1) * 2;
        }
    }
    float hp0 = 0.f, hp1 = 0.f;

    for (int s = 0; s < TT; s++) {
        // XW prefetch (hides DRAM latency under barrier wait)
        float xw0r, xw0z, xw0n, xw1r, xw1z, xw1n;
        {
            const float* p0 = a.XW + ((size_t)s * 64 + rowI) * G3 + u0 + uI;
            const float* p1 = p0 + (size_t)32 * G3;
            xw0r = p0[0]; xw0z = p0[512]; xw0n = p0[1024];
            xw1r = p1[0]; xw1z = p1[512]; xw1n = p1[1024];
        }

        // wait for all h_{s-1} (parallel poll, no atomic contention)
        if (warp == 0) {
            const unsigned tgt = (unsigned)(s + 1);
            for (;;) {
                unsigned v0 = ld_acq(fp0);
                unsigned v1 = ld_acq(fp1);
                if (__all_sync(0xffffffffu, v0 >= tgt && v1 >= tgt)) break;
            }
        }
        __syncthreads();

        // prefetch ALL A-fragments (32 x LDG.128, MLP-batched)
        const uint4* rb = (s & 1) ? a.hb0 : a.hb1;
        uint4 AH[16], AL[16];
        {
            const uint4* base = rb + (kh * 16 * 4 + mt) * 32 + lane;
#pragma unroll
            for (int kt = 0; kt < 16; kt++) {
                AH[kt] = base[kt * 128];
                AL[kt] = base[kt * 128 + 4096];
            }
        }

        float acc[3][4];
#pragma unroll
        for (int nt = 0; nt < 3; nt++)
#pragma unroll
            for (int q = 0; q < 4; q++) acc[nt][q] = 0.f;

#pragma unroll
        for (int kt = 0; kt < 16; kt++) {
            const int k8a = kh * 32 + kt * 2;
            uint32_t bh6[6], bl6[6];
            {
                int k8 = k8a + (g & 1);
                int n8 = g >> 1;
                int elem = (k8 * 3 + n8) * 64 + r * 8;
                uint32_t bd = sptr(WhHi + elem);
                LDSM_X4T(bh6[0], bh6[1], bh6[2], bh6[3], bd);
                bd = sptr(WhLo + elem);
                LDSM_X4T(bl6[0], bl6[1], bl6[2], bl6[3], bd);
                int k8c = k8a + g01;
                int elem2 = (k8c * 3 + 2) * 64 + r * 8;
                bd = sptr(WhHi + elem2);
                LDSM_X2T(bh6[4], bh6[5], bd);
                bd = sptr(WhLo + elem2);
                LDSM_X2T(bl6[4], bl6[5], bd);
            }
#pragma unroll
            for (int nt = 0; nt < 3; nt++) {
                float* c = acc[nt];
                MMA16816(c[0], c[1], c[2], c[3],
                         AH[kt].x, AH[kt].y, AH[kt].z, AH[kt].w,
                         bh6[nt * 2], bh6[nt * 2 + 1]);
                MMA16816(c[0], c[1], c[2], c[3],
                         AH[kt].x, AH[kt].y, AH[kt].z, AH[kt].w,
                         bl6[nt * 2], bl6[nt * 2 + 1]);
                MMA16816(c[0], c[1], c[2], c[3],
                         AL[kt].x, AL[kt].y, AL[kt].z, AL[kt].w,
                         bh6[nt * 2], bh6[nt * 2 + 1]);
            }
        }

        // write partials to smem
        {
            float* pb = part + kh * 1600;
            int prow = mt * 16 + (lane >> 2);
            int pc = (lane & 3) * 2;
#pragma unroll
            for (int nt = 0; nt < 3; nt++) {
                pb[prow * 25 + nt * 8 + pc]     = acc[nt][0];
                pb[prow * 25 + nt * 8 + pc + 1] = acc[nt][1];
                pb[(prow + 8) * 25 + nt * 8 + pc]     = acc[nt][2];
                pb[(prow + 8) * 25 + nt * 8 + pc + 1] = acc[nt][3];
            }
        }
        __syncthreads();

        // gates: 2 items per thread (rows rowI, rowI+32; unit uI)
        char* wb = (char*)((s & 1) ? a.hb1 : a.hb0);
        float hn0, hn1;
#pragma unroll
        for (int q = 0; q < 2; q++) {
            int row = rowI + q * 32;
            float gr = part[row * 25 + cb]     + part[1600 + row * 25 + cb];
            float gz = part[row * 25 + cb + 1] + part[1600 + row * 25 + cb + 1];
            float gn = part[row * 25 + cb + 2] + part[1600 + row * 25 + cb + 2];
            float xr = q ? xw1r : xw0r;
            float xz = q ? xw1z : xw0z;
            float xn = q ? xw1n : xw0n;
            float rr = __fdividef(1.f, 1.f + __expf(-(xr + gr + bhr)));
            float zz = __fdividef(1.f, 1.f + __expf(-(xz + gz + bhz)));
            float tt = xn + rr * (gn + bhn);
            float nn = __fdividef(2.f, 1.f + __expf(-2.f * tt)) - 1.f;
            float hp = q ? hp1 : hp0;
            float hn = (1.f - zz) * nn + zz * hp;
            if (q) { hp1 = hn; hn1 = hn; } else { hp0 = hn; hn0 = hn; }
            __nv_bfloat16 hi = __float2bfloat16(hn);
            __nv_bfloat16 lo = __float2bfloat16(hn - __bfloat162float(hi));
            *(__nv_bfloat16*)(wb + oQ[q]) = hi;
            *(__nv_bfloat16*)(wb + 65536 + oQ[q]) = lo;
        }
        __syncthreads();
        if (s < TT - 1 && tid == 0) st_rel(&a.flags[bl * FSTR], (unsigned)(s + 2));

        // OUT (f32) stores off the critical path
        const int oidx = a.rev ? (TT - 1 - s) : s;
        a.OUT[((size_t)oidx * NBATCH + rowI) * HID + u0 + uI] = hn0;
        a.OUT[((size_t)oidx * NBATCH + rowI + 32) * HID + u0 + uI] = hn1;
    }
}

// reset barrier flags for graph-replay determinism
__global__ void reset_flags_kernel()
{
    int i = blockIdx.x * blockDim.x + threadIdx.x;
    if (i < 4 * 64 * FSTR) ((unsigned*)g_flags)[i] = 0u;
}

// ---------------------------------------------------------------------------
// msg / lasth
// ---------------------------------------------------------------------------
__global__ void msg_kernel(const float* __restrict__ h, float* __restrict__ msg)
{
    int idx = blockIdx.x * blockDim.x + threadIdx.x;
    if (idx >= NBATCH * HID) return;
    int n = idx >> 9, j = idx & 511;
    int b = n >> 3;
    float s = 0.f;
#pragma unroll
    for (int aa = 0; aa < AAGENT; aa++) s += h[((b << 3) + aa) * HID + j];
    msg[idx] = (s - h[n * HID + j]) * (1.f / (AAGENT - 1));
}

__global__ void lasth_kernel(const float* __restrict__ OUT, float* __restrict__ dst)
{
    int idx = blockIdx.x * blockDim.x + threadIdx.x;
    if (idx >= BBATCH * HID) return;
    int b = idx >> 9, j = idx & 511;
    dst[idx] = OUT[((size_t)(TT - 1) * NBATCH + b * AAGENT) * HID + j];
}

// ---------------------------------------------------------------------------
// launch
// ---------------------------------------------------------------------------
extern "C" void kernel_launch(void* const* d_in, const int* in_sizes, int n_in,
                              void* d_out, int out_size)
{
    const float* article = (const float*)d_in[0];
    const float* Wx_f = (const float*)d_in[2];
    const float* Wh_f = (const float*)d_in[3];
    const float* bx_f = (const float*)d_in[4];
    const float* bh_f = (const float*)d_in[5];
    const float* Wx_b = (const float*)d_in[6];
    const float* Wh_b = (const float*)d_in[7];
    const float* bx_b = (const float*)d_in[8];
    const float* bh_b = (const float*)d_in[9];
    const float* Wp   = (const float*)d_in[10];
    const float* bp   = (const float*)d_in[11];
    const float* Wm   = (const float*)d_in[12];
    const float* bm   = (const float*)d_in[13];
    const float* Wx_c = (const float*)d_in[14];
    const float* Wh_c = (const float*)d_in[15];
    const float* bx_c = (const float*)d_in[16];
    const float* bh_c = (const float*)d_in[17];

    float *XW1, *XW2, *ENCF, *ENCB, *ENC, *hsm, *msg, *msgp;
    uint4* hfrag;
    unsigned* flags;
    cudaGetSymbolAddress((void**)&XW1,  g_XW1);
    cudaGetSymbolAddress((void**)&XW2,  g_XW2);
    cudaGetSymbolAddress((void**)&ENCF, g_ENCF);
    cudaGetSymbolAddress((void**)&ENCB, g_ENCB);
    cudaGetSymbolAddress((void**)&ENC,  g_ENC);
    cudaGetSymbolAddress((void**)&hsm,  g_hsm);
    cudaGetSymbolAddress((void**)&msg,  g_msg);
    cudaGetSymbolAddress((void**)&msgp, g_msgp);
    cudaGetSymbolAddress((void**)&hfrag, g_hfrag);
    cudaGetSymbolAddress((void**)&flags, g_flags);
    uint4* hA0 = hfrag;
    uint4* hA1 = hfrag + 8192;
    uint4* hB0 = hfrag + 16384;
    uint4* hB1 = hfrag + 24576;

    const int M = TT * NBATCH;
    cudaFuncSetAttribute((const void*)gru_tc,
                         cudaFuncAttributeMaxDynamicSharedMemorySize, S_TOTAL);

    // 1) xW precompute for both directions (backward reads time-reversed rows)
    tgemm<<<dim3(G3 / 128, M / 128), 256>>>(article, nullptr, Wx_f, bx_f, nullptr,
                                            XW1, M, DIN, G3, 0);
    tgemm<<<dim3(G3 / 128, M / 128), 256>>>(article, nullptr, Wx_b, bx_b, nullptr,
                                            XW2, M, DIN, G3, 1);

    // 2) bidirectional recurrence (two 64-CTA barrier groups, one launch)
    GruArgs af{XW1, Wh_f, bh_f, ENCF, hA0, hA1, flags + 0 * 64 * FSTR, 0};
    GruArgs ab{XW2, Wh_b, bh_b, ENCB, hB0, hB1, flags + 1 * 64 * FSTR, 1};
    gru_tc<<<128, 256, S_TOTAL>>>(af, ab, 64);

    // 3) projection of per-step encodings and of final hidden
    tgemm<<<dim3(HID / 128, M / 128), 256>>>(ENCF, ENCB, Wp, bp, nullptr,
                                             ENC, M, 2 * HID, HID, 0);
    tgemm<<<dim3(HID / 128, 1), 256>>>(ENCF + (size_t)(TT - 1) * NBATCH * HID, ENCB,
                                       Wp, bp, nullptr, hsm, NBATCH, 2 * HID, HID, 0);

    // 4) communication layers
    for (int l = 0; l < LLAYER; l++) {
        const float* hsrc = (l == 0) ? hsm : (ENC + (size_t)(TT - 1) * NBATCH * HID);
        msg_kernel<<<(NBATCH * HID) / 256, 256>>>(hsrc, msg);
        tgemm<<<dim3(HID / 128, 1), 256>>>(msg, nullptr, Wm + (size_t)512 * HID, bm,
                                           nullptr, msgp, NBATCH, HID, HID, 0);
        tgemm<<<dim3(HID / 128, M / 128), 256>>>(ENC, nullptr, Wm, nullptr, msgp,
                                                 XW2, M, HID, HID, 0);
        tgemm<<<dim3(G3 / 128, M / 128), 256>>>(XW2, nullptr,
                                                Wx_c + (size_t)l * HID * G3,
                                                bx_c + (size_t)l * G3, nullptr,
                                                XW1, M, HID, G3, 0);
        float* outp = (l == LLAYER - 1) ? (float*)d_out : ENC;
        GruArgs ac{XW1, Wh_c + (size_t)l * HID * G3, bh_c + (size_t)l * G3,
                   outp, hA0, hA1, flags + (2 + l) * 64 * FSTR, 0};
        gru_tc<<<64, 256, S_TOTAL>>>(ac, ac, 64);
    }

    // 5) tail output + flag reset for graph replay
    lasth_kernel<<<(BBATCH * HID + 255) / 256, 256>>>(
        (const float*)d_out, (float*)d_out + (size_t)TT * NBATCH * HID);
    reset_flags_kernel<<<32, 256>>>();
}

// round 6
// speedup vs baseline: 2.6387x; 1.0848x over previous
#include <cuda_runtime.h>
#include <cuda_bf16.h>
#include <cuda_fp16.h>
#include <math.h>
#include <stdint.h>

// Problem constants
#define TT 512
#define NBATCH 64      // B*A
#define HID 512
#define DIN 512
#define G3 1536        // 3*HID
#define BBATCH 8
#define AAGENT 8
#define LLAYER 2

// ---------------------------------------------------------------------------
// Scratch (device globals; no allocations allowed)
// ---------------------------------------------------------------------------
__device__ float g_XW1[(size_t)TT * NBATCH * G3];   // 192 MB
__device__ float g_XW2[(size_t)TT * NBATCH * G3];   // 192 MB
__device__ float g_ENCF[(size_t)TT * NBATCH * HID]; // 64 MB
__device__ float g_ENCB[(size_t)TT * NBATCH * HID]; // 64 MB
__device__ float g_ENC [(size_t)TT * NBATCH * HID]; // 64 MB
__device__ float g_hsm [NBATCH * HID];
__device__ float g_msg [NBATCH * HID];
__device__ float g_msgp[NBATCH * HID];
// h in mma A-fragment layout (fp16), double-buffered per group.
// [group][parity][4096 uint4]  (64 KB each)
__device__ uint4 g_hfrag[2][2][4096];
// distributed barrier flags: 4 groups x 64 CTAs x 128B slots
#define FSTR 32
__device__ unsigned g_flags[4][64 * FSTR];

// ---------------------------------------------------------------------------
// barrier primitives
// ---------------------------------------------------------------------------
__device__ __forceinline__ unsigned ld_acq(const unsigned* p) {
    unsigned v;
    asm volatile("ld.acquire.gpu.global.u32 %0, [%1];" : "=r"(v) : "l"(p) : "memory");
    return v;
}
__device__ __forceinline__ void st_rel(unsigned* p, unsigned v) {
    asm volatile("st.release.gpu.global.u32 [%0], %1;" :: "l"(p), "r"(v) : "memory");
}

// ---------------------------------------------------------------------------
// mma helpers
// ---------------------------------------------------------------------------
__device__ __forceinline__ uint32_t sptr(const void* p) {
    return (uint32_t)__cvta_generic_to_shared(p);
}

#define LDSM_X4T(R0, R1, R2, R3, ADDR)                                         \
    asm volatile("ldmatrix.sync.aligned.m8n8.x4.trans.shared.b16 "             \
                 "{%0,%1,%2,%3},[%4];"                                         \
                 : "=r"(R0), "=r"(R1), "=r"(R2), "=r"(R3) : "r"(ADDR))

#define LDSM_X4(R0, R1, R2, R3, ADDR)                                          \
    asm volatile("ldmatrix.sync.aligned.m8n8.x4.shared.b16 {%0,%1,%2,%3},[%4];"\
                 : "=r"(R0), "=r"(R1), "=r"(R2), "=r"(R3) : "r"(ADDR))

#define LDSM_X2T(R0, R1, ADDR)                                                 \
    asm volatile("ldmatrix.sync.aligned.m8n8.x2.trans.shared.b16 {%0,%1},[%2];"\
                 : "=r"(R0), "=r"(R1) : "r"(ADDR))

#define MMA16816(C0, C1, C2, C3, A0, A1, A2_, A3, B0, B1)                      \
    asm volatile("mma.sync.aligned.m16n8k16.row.col.f32.bf16.bf16.f32 "        \
                 "{%0,%1,%2,%3},{%4,%5,%6,%7},{%8,%9},{%0,%1,%2,%3};"          \
                 : "+f"(C0), "+f"(C1), "+f"(C2), "+f"(C3)                      \
                 : "r"(A0), "r"(A1), "r"(A2_), "r"(A3), "r"(B0), "r"(B1))

#define MMAF16(C0, C1, C2, C3, A0, A1, A2_, A3, B0, B1)                        \
    asm volatile("mma.sync.aligned.m16n8k16.row.col.f32.f16.f16.f32 "          \
                 "{%0,%1,%2,%3},{%4,%5,%6,%7},{%8,%9},{%0,%1,%2,%3};"          \
                 : "+f"(C0), "+f"(C1), "+f"(C2), "+f"(C3)                      \
                 : "r"(A0), "r"(A1), "r"(A2_), "r"(A3), "r"(B0), "r"(B1))

// ---------------------------------------------------------------------------
// Tensor-core GEMM (bf16 3-term split), register-prefetch pipeline.
// ---------------------------------------------------------------------------
__global__ __launch_bounds__(256) void tgemm(
    const float* __restrict__ A, const float* __restrict__ A2,
    const float* __restrict__ Bm, const float* __restrict__ bias,
    const float* __restrict__ rowAdd, float* __restrict__ C,
    int M, int K, int Nc, int revT)
{
    __shared__ __nv_bfloat16 Ah[4096], Al[4096], Bh[4096], Bl[4096];

    const int tid  = threadIdx.x;
    const int lane = tid & 31;
    const int warp = tid >> 5;
    const int warpM = warp >> 2;
    const int warpN = warp & 3;
    const int row0 = blockIdx.y * 128;
    const int col0 = blockIdx.x * 128;
    const int lda = (A2 != nullptr) ? 512 : K;

    float acc[4][4][4];
#pragma unroll
    for (int mt = 0; mt < 4; mt++)
#pragma unroll
        for (int nt = 0; nt < 4; nt++)
#pragma unroll
            for (int q = 0; q < 4; q++) acc[mt][nt][q] = 0.f;

    const int g = lane >> 3, r = lane & 7;

    float2 va[8], vb[8];

    auto loadTiles = [&](int k0) {
#pragma unroll
        for (int e = 0; e < 8; e++) {
            int id = e * 256 + tid;
            int m  = id >> 4;
            int k  = (id & 15) << 1;
            float2 v = make_float2(0.f, 0.f);
            int gm = row0 + m;
            if (gm < M) {
                int kk = k0 + k;
                const float* Ap = A;
                int ka = kk;
                if (A2 != nullptr && kk >= 512) { Ap = A2; ka = kk - 512; }
                int mp = gm;
                if (revT) mp = (511 - (gm >> 6)) * 64 + (gm & 63);
                v = *(const float2*)(Ap + (size_t)mp * lda + ka);
            }
            va[e] = v;
        }
#pragma unroll
        for (int e = 0; e < 8; e++) {
            int id = e * 256 + tid;
            int k  = id >> 6;
            int n  = (id & 63) << 1;
            vb[e] = *(const float2*)(Bm + (size_t)(k0 + k) * Nc + col0 + n);
        }
    };

    auto storeTiles = [&]() {
#pragma unroll
        for (int e = 0; e < 8; e++) {
            int id = e * 256 + tid;
            int m  = id >> 4;
            int k  = (id & 15) << 1;
            float2 v = va[e];
            __nv_bfloat16 h0 = __float2bfloat16(v.x);
            __nv_bfloat16 h1 = __float2bfloat16(v.y);
            __nv_bfloat16 l0 = __float2bfloat16(v.x - __bfloat162float(h0));
            __nv_bfloat16 l1 = __float2bfloat16(v.y - __bfloat162float(h1));
            int off = (((k >> 3) << 4) + (m >> 3)) * 64 + ((m & 7) << 3) + (k & 7);
            __nv_bfloat162 ph; ph.x = h0; ph.y = h1;
            __nv_bfloat162 pl; pl.x = l0; pl.y = l1;
            *(__nv_bfloat162*)(Ah + off) = ph;
            *(__nv_bfloat162*)(Al + off) = pl;
        }
#pragma unroll
        for (int e = 0; e < 8; e++) {
            int id = e * 256 + tid;
            int k  = id >> 6;
            int n  = (id & 63) << 1;
            float2 v = vb[e];
            __nv_bfloat16 h0 = __float2bfloat16(v.x);
            __nv_bfloat16 h1 = __float2bfloat16(v.y);
            __nv_bfloat16 l0 = __float2bfloat16(v.x - __bfloat162float(h0));
            __nv_bfloat16 l1 = __float2bfloat16(v.y - __bfloat162float(h1));
            int off = (((k >> 3) << 4) + (n >> 3)) * 64 + ((k & 7) << 3) + (n & 7);
            __nv_bfloat162 ph; ph.x = h0; ph.y = h1;
            __nv_bfloat162 pl; pl.x = l0; pl.y = l1;
            *(__nv_bfloat162*)(Bh + off) = ph;
            *(__nv_bfloat162*)(Bl + off) = pl;
        }
    };

    loadTiles(0);

    for (int k0 = 0; k0 < K; k0 += 32) {
        storeTiles();
        __syncthreads();
        if (k0 + 32 < K) loadTiles(k0 + 32);   // overlap with mma below

#pragma unroll
        for (int kc = 0; kc < 2; kc++) {
            uint32_t bh[8], bl[8];
#pragma unroll
            for (int np = 0; np < 2; np++) {
                int k8 = kc * 2 + (g & 1);
                int n8 = warpN * 4 + np * 2 + (g >> 1);
                int elem = (k8 * 16 + n8) * 64 + r * 8;
                uint32_t ad = sptr(Bh + elem);
                LDSM_X4T(bh[np * 4 + 0], bh[np * 4 + 1],
                         bh[np * 4 + 2], bh[np * 4 + 3], ad);
                ad = sptr(Bl + elem);
                LDSM_X4T(bl[np * 4 + 0], bl[np * 4 + 1],
                         bl[np * 4 + 2], bl[np * 4 + 3], ad);
            }
#pragma unroll
            for (int mt = 0; mt < 4; mt++) {
                int m8 = warpM * 8 + mt * 2 + (g & 1);
                int k8 = kc * 2 + (g >> 1);
                int elem = (k8 * 16 + m8) * 64 + r * 8;
                uint32_t ah[4], al[4];
                uint32_t ad = sptr(Ah + elem);
                LDSM_X4(ah[0], ah[1], ah[2], ah[3], ad);
                ad = sptr(Al + elem);
                LDSM_X4(al[0], al[1], al[2], al[3], ad);
#pragma unroll
                for (int nt = 0; nt < 4; nt++) {
                    float* c = acc[mt][nt];
                    MMA16816(c[0], c[1], c[2], c[3],
                             ah[0], ah[1], ah[2], ah[3], bh[nt * 2], bh[nt * 2 + 1]);
                    MMA16816(c[0], c[1], c[2], c[3],
                             ah[0], ah[1], ah[2], ah[3], bl[nt * 2], bl[nt * 2 + 1]);
                    MMA16816(c[0], c[1], c[2], c[3],
                             al[0], al[1], al[2], al[3], bh[nt * 2], bh[nt * 2 + 1]);
                }
            }
        }
        __syncthreads();
    }

#pragma unroll
    for (int mt = 0; mt < 4; mt++) {
#pragma unroll
        for (int nt = 0; nt < 4; nt++) {
            int rA = row0 + warpM * 64 + mt * 16 + (lane >> 2);
            int cg = col0 + warpN * 32 + nt * 8 + ((lane & 3) << 1);
            float b0 = 0.f, b1 = 0.f;
            if (bias) { b0 = bias[cg]; b1 = bias[cg + 1]; }
#pragma unroll
            for (int half = 0; half < 2; half++) {
                int m = rA + half * 8;
                if (m >= M) continue;
                float v0 = acc[mt][nt][half * 2 + 0] + b0;
                float v1 = acc[mt][nt][half * 2 + 1] + b1;
                if (rowAdd) {
                    int rm = (m & 63) * Nc;
                    v0 += rowAdd[rm + cg];
                    v1 += rowAdd[rm + cg + 1];
                }
                float2 o; o.x = v0; o.y = v1;
                *(float2*)(C + (size_t)m * Nc + cg) = o;
            }
        }
    }
}

// ---------------------------------------------------------------------------
// Tensor-core persistent GRU scan: fp16 2-pass recurrent GEMM.
//   h (bounded, |h|<=1) quantized once to fp16 (err ~2^-11); Wh kept as fp16
//   hi + residual lo. g = h_fp16 @ (WhHi + WhLo): 2 mma passes. Recurrence
//   carry stays fp32 in registers. h circulates in a single fp16 fragment
//   buffer (64 KB), double-buffered; distributed-flag barrier.
// ---------------------------------------------------------------------------
struct GruArgs {
    const float* XW;        // [T, 64, 1536]
    const float* Wh;        // [512, 1536]
    const float* bh;        // [1536]
    float* OUT;             // [T, 64, 512]
    uint4* hb0;             // parity-0 fragment buffer (4096 uint4)
    uint4* hb1;             // parity-1
    unsigned* flags;        // [64 * FSTR]
    int rev;
};

// smem byte offsets
#define S_WHHI 0
#define S_WHLO 24576
#define S_PART 49152
#define S_BHS  61952
#define S_TOTAL 62080

__global__ __launch_bounds__(256, 1) void gru_tc(GruArgs a0, GruArgs a1, int cpg)
{
    extern __shared__ char smraw[];
    __half* WhHi = (__half*)(smraw + S_WHHI);
    __half* WhLo = (__half*)(smraw + S_WHLO);
    float* part = (float*)(smraw + S_PART);   // [2][64*25]
    float* bhs  = (float*)(smraw + S_BHS);    // [24]

    const int tid  = threadIdx.x;
    const int lane = tid & 31;
    const int warp = tid >> 5;
    const GruArgs a = (blockIdx.x / cpg == 0) ? a0 : a1;
    const int bl = blockIdx.x % cpg;
    const int u0 = bl * 8;

    // one-time: Wh slice -> smem fp16 hi/lo (ldmatrix-tiled, 3 n8 blocks)
    for (int idx = tid; idx < 512 * 24; idx += 256) {
        int d = idx / 24, c = idx - d * 24;
        int u = c / 3, gg = c - u * 3;
        float v = a.Wh[(size_t)d * G3 + gg * 512 + u0 + u];
        __half hi = __float2half(v);
        __half lo = __float2half(v - __half2float(hi));
        int off = ((d >> 3) * 3 + (c >> 3)) * 64 + (d & 7) * 8 + (c & 7);
        WhHi[off] = hi;
        WhLo[off] = lo;
    }
    if (tid < 24) {
        int u = tid / 3, gg = tid - u * 3;
        bhs[tid] = a.bh[gg * 512 + u0 + u];
    }
    // zero my slice of the parity-1 buffer (h_{-1} = 0)
    {
        int zn = 4096 / cpg;
        uint4 z; z.x = z.y = z.z = z.w = 0u;
        for (int i = tid; i < zn; i += 256) a.hb1[bl * zn + i] = z;
    }
    __syncthreads();
    if (tid == 0) st_rel(&a.flags[bl * FSTR], 1u);

    // per-thread constants
    const int kh = warp >> 2;      // K half (0/1)
    const int mt = warp & 3;       // mtile (rows mt*16..+15)
    const int g  = lane >> 3, r = lane & 7;
    const int g01 = g & 1;
    const int rowI = tid >> 3;     // gate item 0 row (0..31)
    const int uI   = tid & 7;
    const int cb   = uI * 3;
    const float bhr = bhs[cb], bhz = bhs[cb + 1], bhn = bhs[cb + 2];

    // poll addresses for warp 0 (2 slots per lane)
    const unsigned* fp0 = a.flags + (2 * lane) * FSTR;
    const unsigned* fp1 = a.flags + (2 * lane + 1) * FSTR;

    // producer scatter offsets (byte) for q=0,1
    int oQ[2];
    {
        int u = u0 + uI;
        int khp = u >> 8, ktp = (u >> 4) & 15, k_in = u & 15;
#pragma unroll
        for (int q = 0; q < 2; q++) {
            int row = rowI + q * 32;
            int mtp = row >> 4, m_in = row & 15;
            int lanep = (m_in & 7) * 4 + ((k_in & 7) >> 1);
            int regp = ((m_in >> 3) & 1) + (((k_in >> 3) & 1) << 1);
            oQ[q] = ((((khp * 16 + ktp) * 4 + mtp) * 32 + lanep) << 4)
                    + regp * 4 + (k_in & 1) * 2;
        }
    }
    float hp0 = 0.f, hp1 = 0.f;

    for (int s = 0; s < TT; s++) {
        // XW prefetch (hides DRAM latency under barrier wait)
        float xw0r, xw0z, xw0n, xw1r, xw1z, xw1n;
        {
            const float* p0 = a.XW + ((size_t)s * 64 + rowI) * G3 + u0 + uI;
            const float* p1 = p0 + (size_t)32 * G3;
            xw0r = p0[0]; xw0z = p0[512]; xw0n = p0[1024];
            xw1r = p1[0]; xw1z = p1[512]; xw1n = p1[1024];
        }

        // wait for all h_{s-1} (parallel poll, no atomic contention)
        if (warp == 0) {
            const unsigned tgt = (unsigned)(s + 1);
            for (;;) {
                unsigned v0 = ld_acq(fp0);
                unsigned v1 = ld_acq(fp1);
                if (__all_sync(0xffffffffu, v0 >= tgt && v1 >= tgt)) break;
            }
        }
        __syncthreads();

        // prefetch ALL A-fragments (16 x LDG.128, MLP-batched)
        const uint4* rb = (s & 1) ? a.hb0 : a.hb1;
        uint4 AH[16];
        {
            const uint4* base = rb + (kh * 16 * 4 + mt) * 32 + lane;
#pragma unroll
            for (int kt = 0; kt < 16; kt++) AH[kt] = base[kt * 128];
        }

        float acc[3][4];
#pragma unroll
        for (int nt = 0; nt < 3; nt++)
#pragma unroll
            for (int q = 0; q < 4; q++) acc[nt][q] = 0.f;

#pragma unroll
        for (int kt = 0; kt < 16; kt++) {
            const int k8a = kh * 32 + kt * 2;
            uint32_t bh6[6], bl6[6];
            {
                int k8 = k8a + (g & 1);
                int n8 = g >> 1;
                int elem = (k8 * 3 + n8) * 64 + r * 8;
                uint32_t bd = sptr(WhHi + elem);
                LDSM_X4T(bh6[0], bh6[1], bh6[2], bh6[3], bd);
                bd = sptr(WhLo + elem);
                LDSM_X4T(bl6[0], bl6[1], bl6[2], bl6[3], bd);
                int k8c = k8a + g01;
                int elem2 = (k8c * 3 + 2) * 64 + r * 8;
                bd = sptr(WhHi + elem2);
                LDSM_X2T(bh6[4], bh6[5], bd);
                bd = sptr(WhLo + elem2);
                LDSM_X2T(bl6[4], bl6[5], bd);
            }
#pragma unroll
            for (int nt = 0; nt < 3; nt++) {
                float* c = acc[nt];
                MMAF16(c[0], c[1], c[2], c[3],
                       AH[kt].x, AH[kt].y, AH[kt].z, AH[kt].w,
                       bh6[nt * 2], bh6[nt * 2 + 1]);
                MMAF16(c[0], c[1], c[2], c[3],
                       AH[kt].x, AH[kt].y, AH[kt].z, AH[kt].w,
                       bl6[nt * 2], bl6[nt * 2 + 1]);
            }
        }

        // write partials to smem
        {
            float* pb = part + kh * 1600;
            int prow = mt * 16 + (lane >> 2);
            int pc = (lane & 3) * 2;
#pragma unroll
            for (int nt = 0; nt < 3; nt++) {
                pb[prow * 25 + nt * 8 + pc]     = acc[nt][0];
                pb[prow * 25 + nt * 8 + pc + 1] = acc[nt][1];
                pb[(prow + 8) * 25 + nt * 8 + pc]     = acc[nt][2];
                pb[(prow + 8) * 25 + nt * 8 + pc + 1] = acc[nt][3];
            }
        }
        __syncthreads();

        // gates: 2 items per thread (rows rowI, rowI+32; unit uI)
        char* wb = (char*)((s & 1) ? a.hb1 : a.hb0);
        float hn0, hn1;
#pragma unroll
        for (int q = 0; q < 2; q++) {
            int row = rowI + q * 32;
            float gr = part[row * 25 + cb]     + part[1600 + row * 25 + cb];
            float gz = part[row * 25 + cb + 1] + part[1600 + row * 25 + cb + 1];
            float gn = part[row * 25 + cb + 2] + part[1600 + row * 25 + cb + 2];
            float xr = q ? xw1r : xw0r;
            float xz = q ? xw1z : xw0z;
            float xn = q ? xw1n : xw0n;
            float rr = __fdividef(1.f, 1.f + __expf(-(xr + gr + bhr)));
            float zz = __fdividef(1.f, 1.f + __expf(-(xz + gz + bhz)));
            float tt = xn + rr * (gn + bhn);
            float nn = __fdividef(2.f, 1.f + __expf(-2.f * tt)) - 1.f;
            float hp = q ? hp1 : hp0;
            float hn = (1.f - zz) * nn + zz * hp;
            if (q) { hp1 = hn; hn1 = hn; } else { hp0 = hn; hn0 = hn; }
            *(__half*)(wb + oQ[q]) = __float2half(hn);
        }
        __syncthreads();
        if (s < TT - 1 && tid == 0) st_rel(&a.flags[bl * FSTR], (unsigned)(s + 2));

        // OUT (f32) stores off the critical path
        const int oidx = a.rev ? (TT - 1 - s) : s;
        a.OUT[((size_t)oidx * NBATCH + rowI) * HID + u0 + uI] = hn0;
        a.OUT[((size_t)oidx * NBATCH + rowI + 32) * HID + u0 + uI] = hn1;
    }
}

// reset barrier flags for graph-replay determinism
__global__ void reset_flags_kernel()
{
    int i = blockIdx.x * blockDim.x + threadIdx.x;
    if (i < 4 * 64 * FSTR) ((unsigned*)g_flags)[i] = 0u;
}

// ---------------------------------------------------------------------------
// msg / lasth
// ---------------------------------------------------------------------------
__global__ void msg_kernel(const float* __restrict__ h, float* __restrict__ msg)
{
    int idx = blockIdx.x * blockDim.x + threadIdx.x;
    if (idx >= NBATCH * HID) return;
    int n = idx >> 9, j = idx & 511;
    int b = n >> 3;
    float s = 0.f;
#pragma unroll
    for (int aa = 0; aa < AAGENT; aa++) s += h[((b << 3) + aa) * HID + j];
    msg[idx] = (s - h[n * HID + j]) * (1.f / (AAGENT - 1));
}

__global__ void lasth_kernel(const float* __restrict__ OUT, float* __restrict__ dst)
{
    int idx = blockIdx.x * blockDim.x + threadIdx.x;
    if (idx >= BBATCH * HID) return;
    int b = idx >> 9, j = idx & 511;
    dst[idx] = OUT[((size_t)(TT - 1) * NBATCH + b * AAGENT) * HID + j];
}

// ---------------------------------------------------------------------------
// launch
// ---------------------------------------------------------------------------
extern "C" void kernel_launch(void* const* d_in, const int* in_sizes, int n_in,
                              void* d_out, int out_size)
{
    const float* article = (const float*)d_in[0];
    const float* Wx_f = (const float*)d_in[2];
    const float* Wh_f = (const float*)d_in[3];
    const float* bx_f = (const float*)d_in[4];
    const float* bh_f = (const float*)d_in[5];
    const float* Wx_b = (const float*)d_in[6];
    const float* Wh_b = (const float*)d_in[7];
    const float* bx_b = (const float*)d_in[8];
    const float* bh_b = (const float*)d_in[9];
    const float* Wp   = (const float*)d_in[10];
    const float* bp   = (const float*)d_in[11];
    const float* Wm   = (const float*)d_in[12];
    const float* bm   = (const float*)d_in[13];
    const float* Wx_c = (const float*)d_in[14];
    const float* Wh_c = (const float*)d_in[15];
    const float* bx_c = (const float*)d_in[16];
    const float* bh_c = (const float*)d_in[17];

    float *XW1, *XW2, *ENCF, *ENCB, *ENC, *hsm, *msg, *msgp;
    uint4* hfrag;
    unsigned* flags;
    cudaGetSymbolAddress((void**)&XW1,  g_XW1);
    cudaGetSymbolAddress((void**)&XW2,  g_XW2);
    cudaGetSymbolAddress((void**)&ENCF, g_ENCF);
    cudaGetSymbolAddress((void**)&ENCB, g_ENCB);
    cudaGetSymbolAddress((void**)&ENC,  g_ENC);
    cudaGetSymbolAddress((void**)&hsm,  g_hsm);
    cudaGetSymbolAddress((void**)&msg,  g_msg);
    cudaGetSymbolAddress((void**)&msgp, g_msgp);
    cudaGetSymbolAddress((void**)&hfrag, g_hfrag);
    cudaGetSymbolAddress((void**)&flags, g_flags);
    uint4* hA0 = hfrag;
    uint4* hA1 = hfrag + 4096;
    uint4* hB0 = hfrag + 8192;
    uint4* hB1 = hfrag + 12288;

    const int M = TT * NBATCH;
    cudaFuncSetAttribute((const void*)gru_tc,
                         cudaFuncAttributeMaxDynamicSharedMemorySize, S_TOTAL);

    // 1) xW precompute for both directions (backward reads time-reversed rows)
    tgemm<<<dim3(G3 / 128, M / 128), 256>>>(article, nullptr, Wx_f, bx_f, nullptr,
                                            XW1, M, DIN, G3, 0);
    tgemm<<<dim3(G3 / 128, M / 128), 256>>>(article, nullptr, Wx_b, bx_b, nullptr,
                                            XW2, M, DIN, G3, 1);

    // 2) bidirectional recurrence (two 64-CTA barrier groups, one launch)
    GruArgs af{XW1, Wh_f, bh_f, ENCF, hA0, hA1, flags + 0 * 64 * FSTR, 0};
    GruArgs ab{XW2, Wh_b, bh_b, ENCB, hB0, hB1, flags + 1 * 64 * FSTR, 1};
    gru_tc<<<128, 256, S_TOTAL>>>(af, ab, 64);

    // 3) projection of per-step encodings and of final hidden
    tgemm<<<dim3(HID / 128, M / 128), 256>>>(ENCF, ENCB, Wp, bp, nullptr,
                                             ENC, M, 2 * HID, HID, 0);
    tgemm<<<dim3(HID / 128, 1), 256>>>(ENCF + (size_t)(TT - 1) * NBATCH * HID, ENCB,
                                       Wp, bp, nullptr, hsm, NBATCH, 2 * HID, HID, 0);

    // 4) communication layers
    for (int l = 0; l < LLAYER; l++) {
        const float* hsrc = (l == 0) ? hsm : (ENC + (size_t)(TT - 1) * NBATCH * HID);
        msg_kernel<<<(NBATCH * HID) / 256, 256>>>(hsrc, msg);
        tgemm<<<dim3(HID / 128, 1), 256>>>(msg, nullptr, Wm + (size_t)512 * HID, bm,
                                           nullptr, msgp, NBATCH, HID, HID, 0);
        tgemm<<<dim3(HID / 128, M / 128), 256>>>(ENC, nullptr, Wm, nullptr, msgp,
                                                 XW2, M, HID, HID, 0);
        tgemm<<<dim3(G3 / 128, M / 128), 256>>>(XW2, nullptr,
                                                Wx_c + (size_t)l * HID * G3,
                                                bx_c + (size_t)l * G3, nullptr,
                                                XW1, M, HID, G3, 0);
        float* outp = (l == LLAYER - 1) ? (float*)d_out : ENC;
        GruArgs ac{XW1, Wh_c + (size_t)l * HID * G3, bh_c + (size_t)l * G3,
                   outp, hA0, hA1, flags + (2 + l) * 64 * FSTR, 0};
        gru_tc<<<64, 256, S_TOTAL>>>(ac, ac, 64);
    }

    // 5) tail output + flag reset for graph replay
    lasth_kernel<<<(BBATCH * HID + 255) / 256, 256>>>(
        (const float*)d_out, (float*)d_out + (size_t)TT * NBATCH * HID);
    reset_flags_kernel<<<32, 256>>>();
}

// round 7
// speedup vs baseline: 3.0791x; 1.1669x over previous
#include <cuda_runtime.h>
#include <cuda_bf16.h>
#include <cuda_fp16.h>
#include <math.h>
#include <stdint.h>

// Problem constants
#define TT 512
#define NBATCH 64      // B*A
#define HID 512
#define DIN 512
#define G3 1536        // 3*HID
#define BBATCH 8
#define AAGENT 8
#define LLAYER 2

// ---------------------------------------------------------------------------
// Scratch (device globals; no allocations allowed)
// ---------------------------------------------------------------------------
__device__ float g_XW1[(size_t)TT * NBATCH * G3];   // 192 MB
__device__ float g_XW2[(size_t)TT * NBATCH * G3];   // 192 MB
__device__ float g_ENCF[(size_t)TT * NBATCH * HID]; // 64 MB
__device__ float g_ENCB[(size_t)TT * NBATCH * HID]; // 64 MB
__device__ float g_ENC [(size_t)TT * NBATCH * HID]; // 64 MB
__device__ float g_hsm [NBATCH * HID];
__device__ float g_msg [NBATCH * HID];
__device__ float g_msgp[NBATCH * HID];
__device__ float g_msgrow[NBATCH * G3];             // msgp@Wx_c + bx_c
__device__ float g_Wcomb[LLAYER][(size_t)HID * G3]; // Wm[:512]@Wx_c
// h in mma A-fragment layout (fp16), double-buffered per group.
__device__ uint4 g_hfrag[2][2][4096];
// distributed barrier flags: 4 groups x 64 CTAs x 128B slots
#define FSTR 32
__device__ unsigned g_flags[4][64 * FSTR];
// per-layer chunk-ready counters (256 chunks of 2 timesteps)
__device__ unsigned g_chunk[LLAYER][256];

// ---------------------------------------------------------------------------
// barrier primitives
// ---------------------------------------------------------------------------
__device__ __forceinline__ unsigned ld_acq(const unsigned* p) {
    unsigned v;
    asm volatile("ld.acquire.gpu.global.u32 %0, [%1];" : "=r"(v) : "l"(p) : "memory");
    return v;
}
__device__ __forceinline__ void st_rel(unsigned* p, unsigned v) {
    asm volatile("st.release.gpu.global.u32 [%0], %1;" :: "l"(p), "r"(v) : "memory");
}
__device__ __forceinline__ void red_add_rel(unsigned* p, unsigned v) {
    asm volatile("red.release.gpu.global.add.u32 [%0], %1;" :: "l"(p), "r"(v) : "memory");
}

// ---------------------------------------------------------------------------
// mma helpers
// ---------------------------------------------------------------------------
__device__ __forceinline__ uint32_t sptr(const void* p) {
    return (uint32_t)__cvta_generic_to_shared(p);
}

#define LDSM_X4T(R0, R1, R2, R3, ADDR)                                         \
    asm volatile("ldmatrix.sync.aligned.m8n8.x4.trans.shared.b16 "             \
                 "{%0,%1,%2,%3},[%4];"                                         \
                 : "=r"(R0), "=r"(R1), "=r"(R2), "=r"(R3) : "r"(ADDR))

#define LDSM_X4(R0, R1, R2, R3, ADDR)                                          \
    asm volatile("ldmatrix.sync.aligned.m8n8.x4.shared.b16 {%0,%1,%2,%3},[%4];"\
                 : "=r"(R0), "=r"(R1), "=r"(R2), "=r"(R3) : "r"(ADDR))

#define LDSM_X2T(R0, R1, ADDR)                                                 \
    asm volatile("ldmatrix.sync.aligned.m8n8.x2.trans.shared.b16 {%0,%1},[%2];"\
                 : "=r"(R0), "=r"(R1) : "r"(ADDR))

#define MMA16816(C0, C1, C2, C3, A0, A1, A2_, A3, B0, B1)                      \
    asm volatile("mma.sync.aligned.m16n8k16.row.col.f32.bf16.bf16.f32 "        \
                 "{%0,%1,%2,%3},{%4,%5,%6,%7},{%8,%9},{%0,%1,%2,%3};"          \
                 : "+f"(C0), "+f"(C1), "+f"(C2), "+f"(C3)                      \
                 : "r"(A0), "r"(A1), "r"(A2_), "r"(A3), "r"(B0), "r"(B1))

#define MMAF16(C0, C1, C2, C3, A0, A1, A2_, A3, B0, B1)                        \
    asm volatile("mma.sync.aligned.m16n8k16.row.col.f32.f16.f16.f32 "          \
                 "{%0,%1,%2,%3},{%4,%5,%6,%7},{%8,%9},{%0,%1,%2,%3};"          \
                 : "+f"(C0), "+f"(C1), "+f"(C2), "+f"(C3)                      \
                 : "r"(A0), "r"(A1), "r"(A2_), "r"(A3), "r"(B0), "r"(B1))

// ---------------------------------------------------------------------------
// Tensor-core GEMM body (bf16 3-term split ~= fp32 precision), one 128x128
// tile. Callable from standalone kernel and from producer CTAs.
// ---------------------------------------------------------------------------
__device__ void tgemm_body(
    char* smbase,
    const float* __restrict__ A, const float* __restrict__ A2,
    const float* __restrict__ Bm, const float* __restrict__ bias,
    const float* __restrict__ rowAdd, float* __restrict__ C,
    int M, int K, int Nc, int revT, int bxIdx, int byIdx)
{
    __nv_bfloat16* Ah = (__nv_bfloat16*)smbase;
    __nv_bfloat16* Al = Ah + 4096;
    __nv_bfloat16* Bh = Al + 4096;
    __nv_bfloat16* Bl = Bh + 4096;

    const int tid  = threadIdx.x;
    const int lane = tid & 31;
    const int warp = tid >> 5;
    const int warpM = warp >> 2;
    const int warpN = warp & 3;
    const int row0 = byIdx * 128;
    const int col0 = bxIdx * 128;
    const int lda = (A2 != nullptr) ? 512 : K;

    float acc[4][4][4];
#pragma unroll
    for (int mt = 0; mt < 4; mt++)
#pragma unroll
        for (int nt = 0; nt < 4; nt++)
#pragma unroll
            for (int q = 0; q < 4; q++) acc[mt][nt][q] = 0.f;

    const int g = lane >> 3, r = lane & 7;

    float2 va[8], vb[8];

    auto loadTiles = [&](int k0) {
#pragma unroll
        for (int e = 0; e < 8; e++) {
            int id = e * 256 + tid;
            int m  = id >> 4;
            int k  = (id & 15) << 1;
            float2 v = make_float2(0.f, 0.f);
            int gm = row0 + m;
            if (gm < M) {
                int kk = k0 + k;
                const float* Ap = A;
                int ka = kk;
                if (A2 != nullptr && kk >= 512) { Ap = A2; ka = kk - 512; }
                int mp = gm;
                if (revT) mp = (511 - (gm >> 6)) * 64 + (gm & 63);
                v = *(const float2*)(Ap + (size_t)mp * lda + ka);
            }
            va[e] = v;
        }
#pragma unroll
        for (int e = 0; e < 8; e++) {
            int id = e * 256 + tid;
            int k  = id >> 6;
            int n  = (id & 63) << 1;
            vb[e] = *(const float2*)(Bm + (size_t)(k0 + k) * Nc + col0 + n);
        }
    };

    auto storeTiles = [&]() {
#pragma unroll
        for (int e = 0; e < 8; e++) {
            int id = e * 256 + tid;
            int m  = id >> 4;
            int k  = (id & 15) << 1;
            float2 v = va[e];
            __nv_bfloat16 h0 = __float2bfloat16(v.x);
            __nv_bfloat16 h1 = __float2bfloat16(v.y);
            __nv_bfloat16 l0 = __float2bfloat16(v.x - __bfloat162float(h0));
            __nv_bfloat16 l1 = __float2bfloat16(v.y - __bfloat162float(h1));
            int off = (((k >> 3) << 4) + (m >> 3)) * 64 + ((m & 7) << 3) + (k & 7);
            __nv_bfloat162 ph; ph.x = h0; ph.y = h1;
            __nv_bfloat162 pl; pl.x = l0; pl.y = l1;
            *(__nv_bfloat162*)(Ah + off) = ph;
            *(__nv_bfloat162*)(Al + off) = pl;
        }
#pragma unroll
        for (int e = 0; e < 8; e++) {
            int id = e * 256 + tid;
            int k  = id >> 6;
            int n  = (id & 63) << 1;
            float2 v = vb[e];
            __nv_bfloat16 h0 = __float2bfloat16(v.x);
            __nv_bfloat16 h1 = __float2bfloat16(v.y);
            __nv_bfloat16 l0 = __float2bfloat16(v.x - __bfloat162float(h0));
            __nv_bfloat16 l1 = __float2bfloat16(v.y - __bfloat162float(h1));
            int off = (((k >> 3) << 4) + (n >> 3)) * 64 + ((k & 7) << 3) + (n & 7);
            __nv_bfloat162 ph; ph.x = h0; ph.y = h1;
            __nv_bfloat162 pl; pl.x = l0; pl.y = l1;
            *(__nv_bfloat162*)(Bh + off) = ph;
            *(__nv_bfloat162*)(Bl + off) = pl;
        }
    };

    loadTiles(0);

    for (int k0 = 0; k0 < K; k0 += 32) {
        storeTiles();
        __syncthreads();
        if (k0 + 32 < K) loadTiles(k0 + 32);   // overlap with mma below

#pragma unroll
        for (int kc = 0; kc < 2; kc++) {
            uint32_t bh[8], bl[8];
#pragma unroll
            for (int np = 0; np < 2; np++) {
                int k8 = kc * 2 + (g & 1);
                int n8 = warpN * 4 + np * 2 + (g >> 1);
                int elem = (k8 * 16 + n8) * 64 + r * 8;
                uint32_t ad = sptr(Bh + elem);
                LDSM_X4T(bh[np * 4 + 0], bh[np * 4 + 1],
                         bh[np * 4 + 2], bh[np * 4 + 3], ad);
                ad = sptr(Bl + elem);
                LDSM_X4T(bl[np * 4 + 0], bl[np * 4 + 1],
                         bl[np * 4 + 2], bl[np * 4 + 3], ad);
            }
#pragma unroll
            for (int mt = 0; mt < 4; mt++) {
                int m8 = warpM * 8 + mt * 2 + (g & 1);
                int k8 = kc * 2 + (g >> 1);
                int elem = (k8 * 16 + m8) * 64 + r * 8;
                uint32_t ah[4], al[4];
                uint32_t ad = sptr(Ah + elem);
                LDSM_X4(ah[0], ah[1], ah[2], ah[3], ad);
                ad = sptr(Al + elem);
                LDSM_X4(al[0], al[1], al[2], al[3], ad);
#pragma unroll
                for (int nt = 0; nt < 4; nt++) {
                    float* c = acc[mt][nt];
                    MMA16816(c[0], c[1], c[2], c[3],
                             ah[0], ah[1], ah[2], ah[3], bh[nt * 2], bh[nt * 2 + 1]);
                    MMA16816(c[0], c[1], c[2], c[3],
                             ah[0], ah[1], ah[2], ah[3], bl[nt * 2], bl[nt * 2 + 1]);
                    MMA16816(c[0], c[1], c[2], c[3],
                             al[0], al[1], al[2], al[3], bh[nt * 2], bh[nt * 2 + 1]);
                }
            }
        }
        __syncthreads();
    }

#pragma unroll
    for (int mt = 0; mt < 4; mt++) {
#pragma unroll
        for (int nt = 0; nt < 4; nt++) {
            int rA = row0 + warpM * 64 + mt * 16 + (lane >> 2);
            int cg = col0 + warpN * 32 + nt * 8 + ((lane & 3) << 1);
            float b0 = 0.f, b1 = 0.f;
            if (bias) { b0 = bias[cg]; b1 = bias[cg + 1]; }
#pragma unroll
            for (int half = 0; half < 2; half++) {
                int m = rA + half * 8;
                if (m >= M) continue;
                float v0 = acc[mt][nt][half * 2 + 0] + b0;
                float v1 = acc[mt][nt][half * 2 + 1] + b1;
                if (rowAdd) {
                    int rm = (m & 63) * Nc;
                    v0 += rowAdd[rm + cg];
                    v1 += rowAdd[rm + cg + 1];
                }
                float2 o; o.x = v0; o.y = v1;
                *(float2*)(C + (size_t)m * Nc + cg) = o;
            }
        }
    }
}

__global__ __launch_bounds__(256) void tgemm(
    const float* A, const float* A2, const float* Bm, const float* bias,
    const float* rowAdd, float* C, int M, int K, int Nc, int revT)
{
    extern __shared__ char smem[];
    tgemm_body(smem, A, A2, Bm, bias, rowAdd, C, M, K, Nc, revT,
               blockIdx.x, blockIdx.y);
}

// ---------------------------------------------------------------------------
// Persistent GRU scanner (fp16 2-pass recurrent GEMM); optional per-chunk
// gating on producer-generated XW (fused mode).
// ---------------------------------------------------------------------------
struct GruArgs {
    const float* XW;        // [T, 64, 1536]
    const float* Wh;        // [512, 1536]
    const float* bh;        // [1536]
    float* OUT;             // [T, 64, 512]
    uint4* hb0;             // parity-0 fragment buffer (4096 uint4)
    uint4* hb1;             // parity-1
    unsigned* flags;        // [64 * FSTR]
    int rev;
};

struct ProdArgs {
    const float* A;         // enc input [32768, 512]
    const float* B;         // Wcomb [512, 1536]
    const float* rowAdd;    // msgRow [64, 1536]
    float* C;               // XW out
    unsigned* chunk;        // [256]
    int nProd;
};

// smem byte offsets (scanner)
#define S_WHHI 0
#define S_WHLO 24576
#define S_PART 49152
#define S_BHS  61952
#define S_TOTAL 62080

__device__ void gru_scan(char* smraw, const GruArgs a, int cpg, int bl,
                         const unsigned* chunk)
{
    __half* WhHi = (__half*)(smraw + S_WHHI);
    __half* WhLo = (__half*)(smraw + S_WHLO);
    float* part = (float*)(smraw + S_PART);   // [2][64*25]
    float* bhs  = (float*)(smraw + S_BHS);    // [24]

    const int tid  = threadIdx.x;
    const int lane = tid & 31;
    const int warp = tid >> 5;
    const int u0 = bl * 8;

    // one-time: Wh slice -> smem fp16 hi/lo (ldmatrix-tiled, 3 n8 blocks)
    for (int idx = tid; idx < 512 * 24; idx += 256) {
        int d = idx / 24, c = idx - d * 24;
        int u = c / 3, gg = c - u * 3;
        float v = a.Wh[(size_t)d * G3 + gg * 512 + u0 + u];
        __half hi = __float2half(v);
        __half lo = __float2half(v - __half2float(hi));
        int off = ((d >> 3) * 3 + (c >> 3)) * 64 + (d & 7) * 8 + (c & 7);
        WhHi[off] = hi;
        WhLo[off] = lo;
    }
    if (tid < 24) {
        int u = tid / 3, gg = tid - u * 3;
        bhs[tid] = a.bh[gg * 512 + u0 + u];
    }
    // zero my slice of the parity-1 buffer (h_{-1} = 0)
    {
        int zn = 4096 / cpg;
        uint4 z; z.x = z.y = z.z = z.w = 0u;
        for (int i = tid; i < zn; i += 256) a.hb1[bl * zn + i] = z;
    }
    __syncthreads();
    if (tid == 0) st_rel(&a.flags[bl * FSTR], 1u);

    // per-thread constants
    const int kh = warp >> 2;      // K half (0/1)
    const int mt = warp & 3;       // mtile (rows mt*16..+15)
    const int g  = lane >> 3, r = lane & 7;
    const int g01 = g & 1;
    const int rowI = tid >> 3;     // gate item 0 row (0..31)
    const int uI   = tid & 7;
    const int cb   = uI * 3;
    const float bhr = bhs[cb], bhz = bhs[cb + 1], bhn = bhs[cb + 2];

    // poll addresses for warp 0 (2 slots per lane)
    const unsigned* fp0 = a.flags + (2 * lane) * FSTR;
    const unsigned* fp1 = a.flags + (2 * lane + 1) * FSTR;

    // producer scatter offsets (byte) for q=0,1
    int oQ[2];
    {
        int u = u0 + uI;
        int khp = u >> 8, ktp = (u >> 4) & 15, k_in = u & 15;
#pragma unroll
        for (int q = 0; q < 2; q++) {
            int row = rowI + q * 32;
            int mtp = row >> 4, m_in = row & 15;
            int lanep = (m_in & 7) * 4 + ((k_in & 7) >> 1);
            int regp = ((m_in >> 3) & 1) + (((k_in >> 3) & 1) << 1);
            oQ[q] = ((((khp * 16 + ktp) * 4 + mtp) * 32 + lanep) << 4)
                    + regp * 4 + (k_in & 1) * 2;
        }
    }
    float hp0 = 0.f, hp1 = 0.f;

    for (int s = 0; s < TT; s++) {
        float xw0r, xw0z, xw0n, xw1r, xw1z, xw1n;
        auto loadXW = [&]() {
            const float* p0 = a.XW + ((size_t)s * 64 + rowI) * G3 + u0 + uI;
            const float* p1 = p0 + (size_t)32 * G3;
            xw0r = p0[0]; xw0z = p0[512]; xw0n = p0[1024];
            xw1r = p1[0]; xw1z = p1[512]; xw1n = p1[1024];
        };
        if (!chunk) loadXW();   // bidir: prefetch hides under barrier wait

        // wait: all h_{s-1} published (and XW chunk ready in fused mode)
        if (warp == 0) {
            const unsigned tgt = (unsigned)(s + 1);
            if (chunk) {
                const unsigned* cc = &chunk[s >> 1];
                for (;;) {
                    unsigned v0 = ld_acq(fp0);
                    unsigned v1 = ld_acq(fp1);
                    unsigned c0 = ld_acq(cc);
                    if (__all_sync(0xffffffffu,
                                   v0 >= tgt && v1 >= tgt && c0 >= 12u)) break;
                }
            } else {
                for (;;) {
                    unsigned v0 = ld_acq(fp0);
                    unsigned v1 = ld_acq(fp1);
                    if (__all_sync(0xffffffffu, v0 >= tgt && v1 >= tgt)) break;
                }
            }
        }
        __syncthreads();

        // prefetch ALL A-fragments (16 x LDG.128, MLP-batched)
        const uint4* rb = (s & 1) ? a.hb0 : a.hb1;
        uint4 AH[16];
        {
            const uint4* base = rb + (kh * 16 * 4 + mt) * 32 + lane;
#pragma unroll
            for (int kt = 0; kt < 16; kt++) AH[kt] = base[kt * 128];
        }
        if (chunk) loadXW();    // fused: after chunk gate; hides under mma

        float acc[3][4];
#pragma unroll
        for (int nt = 0; nt < 3; nt++)
#pragma unroll
            for (int q = 0; q < 4; q++) acc[nt][q] = 0.f;

#pragma unroll
        for (int kt = 0; kt < 16; kt++) {
            const int k8a = kh * 32 + kt * 2;
            uint32_t bh6[6], bl6[6];
            {
                int k8 = k8a + (g & 1);
                int n8 = g >> 1;
                int elem = (k8 * 3 + n8) * 64 + r * 8;
                uint32_t bd = sptr(WhHi + elem);
                LDSM_X4T(bh6[0], bh6[1], bh6[2], bh6[3], bd);
                bd = sptr(WhLo + elem);
                LDSM_X4T(bl6[0], bl6[1], bl6[2], bl6[3], bd);
                int k8c = k8a + g01;
                int elem2 = (k8c * 3 + 2) * 64 + r * 8;
                bd = sptr(WhHi + elem2);
                LDSM_X2T(bh6[4], bh6[5], bd);
                bd = sptr(WhLo + elem2);
                LDSM_X2T(bl6[4], bl6[5], bd);
            }
#pragma unroll
            for (int nt = 0; nt < 3; nt++) {
                float* c = acc[nt];
                MMAF16(c[0], c[1], c[2], c[3],
                       AH[kt].x, AH[kt].y, AH[kt].z, AH[kt].w,
                       bh6[nt * 2], bh6[nt * 2 + 1]);
                MMAF16(c[0], c[1], c[2], c[3],
                       AH[kt].x, AH[kt].y, AH[kt].z, AH[kt].w,
                       bl6[nt * 2], bl6[nt * 2 + 1]);
            }
        }

        // write partials to smem
        {
            float* pb = part + kh * 1600;
            int prow = mt * 16 + (lane >> 2);
            int pc = (lane & 3) * 2;
#pragma unroll
            for (int nt = 0; nt < 3; nt++) {
                pb[prow * 25 + nt * 8 + pc]     = acc[nt][0];
                pb[prow * 25 + nt * 8 + pc + 1] = acc[nt][1];
                pb[(prow + 8) * 25 + nt * 8 + pc]     = acc[nt][2];
                pb[(prow + 8) * 25 + nt * 8 + pc + 1] = acc[nt][3];
            }
        }
        __syncthreads();

        // gates: 2 items per thread (rows rowI, rowI+32; unit uI)
        char* wb = (char*)((s & 1) ? a.hb1 : a.hb0);
        float hn0, hn1;
#pragma unroll
        for (int q = 0; q < 2; q++) {
            int row = rowI + q * 32;
            float gr = part[row * 25 + cb]     + part[1600 + row * 25 + cb];
            float gz = part[row * 25 + cb + 1] + part[1600 + row * 25 + cb + 1];
            float gn = part[row * 25 + cb + 2] + part[1600 + row * 25 + cb + 2];
            float xr = q ? xw1r : xw0r;
            float xz = q ? xw1z : xw0z;
            float xn = q ? xw1n : xw0n;
            float rr = __fdividef(1.f, 1.f + __expf(-(xr + gr + bhr)));
            float zz = __fdividef(1.f, 1.f + __expf(-(xz + gz + bhz)));
            float tt = xn + rr * (gn + bhn);
            float nn = __fdividef(2.f, 1.f + __expf(-2.f * tt)) - 1.f;
            float hp = q ? hp1 : hp0;
            float hn = (1.f - zz) * nn + zz * hp;
            if (q) { hp1 = hn; hn1 = hn; } else { hp0 = hn; hn0 = hn; }
            *(__half*)(wb + oQ[q]) = __float2half(hn);
        }
        __syncthreads();
        if (s < TT - 1 && tid == 0) st_rel(&a.flags[bl * FSTR], (unsigned)(s + 2));

        // OUT (f32) stores off the critical path
        const int oidx = a.rev ? (TT - 1 - s) : s;
        a.OUT[((size_t)oidx * NBATCH + rowI) * HID + u0 + uI] = hn0;
        a.OUT[((size_t)oidx * NBATCH + rowI + 32) * HID + u0 + uI] = hn1;
    }
}

__global__ __launch_bounds__(256, 1) void gru_tc(GruArgs a0, GruArgs a1, int cpg)
{
    extern __shared__ char smraw[];
    const bool second = (blockIdx.x / cpg) != 0;
    gru_scan(smraw, second ? a1 : a0, cpg, blockIdx.x % cpg, nullptr);
}

// Fused comm-layer kernel: CTAs 0..63 scan; CTAs 64..147 produce XW tiles in
// timestep order, publishing per-chunk (2 timesteps) ready counters.
__global__ __launch_bounds__(256, 1) void gru_fused(GruArgs a, ProdArgs pr)
{
    extern __shared__ char smraw[];
    if (blockIdx.x < 64) {
        gru_scan(smraw, a, 64, blockIdx.x, pr.chunk);
        return;
    }
    const int p = blockIdx.x - 64;
    for (int t = p; t < 3072; t += pr.nProd) {
        int c = t / 12, n = t - c * 12;
        tgemm_body(smraw, pr.A, nullptr, pr.B, nullptr, pr.rowAdd, pr.C,
                   TT * NBATCH, HID, G3, 0, n, c);
        __threadfence();
        __syncthreads();
        if (threadIdx.x == 0) red_add_rel(&pr.chunk[c], 1u);
    }
}

// reset barrier flags + chunk counters for graph-replay determinism
__global__ void reset_flags_kernel()
{
    int i = blockIdx.x * blockDim.x + threadIdx.x;
    if (i < 4 * 64 * FSTR) ((unsigned*)g_flags)[i] = 0u;
    if (i < LLAYER * 256) ((unsigned*)g_chunk)[i] = 0u;
}

// ---------------------------------------------------------------------------
// msg / lasth
// ---------------------------------------------------------------------------
__global__ void msg_kernel(const float* __restrict__ h, float* __restrict__ msg)
{
    int idx = blockIdx.x * blockDim.x + threadIdx.x;
    if (idx >= NBATCH * HID) return;
    int n = idx >> 9, j = idx & 511;
    int b = n >> 3;
    float s = 0.f;
#pragma unroll
    for (int aa = 0; aa < AAGENT; aa++) s += h[((b << 3) + aa) * HID + j];
    msg[idx] = (s - h[n * HID + j]) * (1.f / (AAGENT - 1));
}

__global__ void lasth_kernel(const float* __restrict__ OUT, float* __restrict__ dst)
{
    int idx = blockIdx.x * blockDim.x + threadIdx.x;
    if (idx >= BBATCH * HID) return;
    int b = idx >> 9, j = idx & 511;
    dst[idx] = OUT[((size_t)(TT - 1) * NBATCH + b * AAGENT) * HID + j];
}

// ---------------------------------------------------------------------------
// launch
// ---------------------------------------------------------------------------
extern "C" void kernel_launch(void* const* d_in, const int* in_sizes, int n_in,
                              void* d_out, int out_size)
{
    const float* article = (const float*)d_in[0];
    const float* Wx_f = (const float*)d_in[2];
    const float* Wh_f = (const float*)d_in[3];
    const float* bx_f = (const float*)d_in[4];
    const float* bh_f = (const float*)d_in[5];
    const float* Wx_b = (const float*)d_in[6];
    const float* Wh_b = (const float*)d_in[7];
    const float* bx_b = (const float*)d_in[8];
    const float* bh_b = (const float*)d_in[9];
    const float* Wp   = (const float*)d_in[10];
    const float* bp   = (const float*)d_in[11];
    const float* Wm   = (const float*)d_in[12];
    const float* bm   = (const float*)d_in[13];
    const float* Wx_c = (const float*)d_in[14];
    const float* Wh_c = (const float*)d_in[15];
    const float* bx_c = (const float*)d_in[16];
    const float* bh_c = (const float*)d_in[17];

    float *XW1, *XW2, *ENCF, *ENCB, *ENC, *hsm, *msg, *msgp, *msgrow, *Wcomb;
    uint4* hfrag;
    unsigned *flags, *chunks;
    cudaGetSymbolAddress((void**)&XW1,  g_XW1);
    cudaGetSymbolAddress((void**)&XW2,  g_XW2);
    cudaGetSymbolAddress((void**)&ENCF, g_ENCF);
    cudaGetSymbolAddress((void**)&ENCB, g_ENCB);
    cudaGetSymbolAddress((void**)&ENC,  g_ENC);
    cudaGetSymbolAddress((void**)&hsm,  g_hsm);
    cudaGetSymbolAddress((void**)&msg,  g_msg);
    cudaGetSymbolAddress((void**)&msgp, g_msgp);
    cudaGetSymbolAddress((void**)&msgrow, g_msgrow);
    cudaGetSymbolAddress((void**)&Wcomb, g_Wcomb);
    cudaGetSymbolAddress((void**)&hfrag, g_hfrag);
    cudaGetSymbolAddress((void**)&flags, g_flags);
    cudaGetSymbolAddress((void**)&chunks, g_chunk);
    uint4* hA0 = hfrag;
    uint4* hA1 = hfrag + 4096;
    uint4* hB0 = hfrag + 8192;
    uint4* hB1 = hfrag + 12288;

    const int M = TT * NBATCH;
    const int SMG = 32768;
    cudaFuncSetAttribute((const void*)gru_tc,
                         cudaFuncAttributeMaxDynamicSharedMemorySize, S_TOTAL);
    cudaFuncSetAttribute((const void*)gru_fused,
                         cudaFuncAttributeMaxDynamicSharedMemorySize, S_TOTAL);

    // 0) Wcomb[l] = Wm[:512] @ Wx_c[l]  (weight folding; tiny)
    for (int l = 0; l < LLAYER; l++)
        tgemm<<<dim3(12, 4), 256, SMG>>>(Wm, nullptr, Wx_c + (size_t)l * HID * G3,
                                         nullptr, nullptr,
                                         Wcomb + (size_t)l * HID * G3,
                                         HID, HID, G3, 0);

    // 1) xW precompute for both directions (backward reads time-reversed rows)
    tgemm<<<dim3(G3 / 128, M / 128), 256, SMG>>>(article, nullptr, Wx_f, bx_f,
                                                 nullptr, XW1, M, DIN, G3, 0);
    tgemm<<<dim3(G3 / 128, M / 128), 256, SMG>>>(article, nullptr, Wx_b, bx_b,
                                                 nullptr, XW2, M, DIN, G3, 1);

    // 2) bidirectional recurrence (two 64-CTA barrier groups, one launch)
    GruArgs af{XW1, Wh_f, bh_f, ENCF, hA0, hA1, flags + 0 * 64 * FSTR, 0};
    GruArgs ab{XW2, Wh_b, bh_b, ENCB, hB0, hB1, flags + 1 * 64 * FSTR, 1};
    gru_tc<<<128, 256, S_TOTAL>>>(af, ab, 64);

    // 3) projection of per-step encodings and of final hidden
    tgemm<<<dim3(HID / 128, M / 128), 256, SMG>>>(ENCF, ENCB, Wp, bp, nullptr,
                                                  ENC, M, 2 * HID, HID, 0);
    tgemm<<<dim3(HID / 128, 1), 256, SMG>>>(ENCF + (size_t)(TT - 1) * NBATCH * HID,
                                            ENCB, Wp, bp, nullptr, hsm,
                                            NBATCH, 2 * HID, HID, 0);

    // 4) communication layers (fused producer/scanner)
    for (int l = 0; l < LLAYER; l++) {
        const float* hsrc = (l == 0) ? hsm : (ENC + (size_t)(TT - 1) * NBATCH * HID);
        msg_kernel<<<(NBATCH * HID) / 256, 256>>>(hsrc, msg);
        tgemm<<<dim3(HID / 128, 1), 256, SMG>>>(msg, nullptr,
                                                Wm + (size_t)512 * HID, bm,
                                                nullptr, msgp, NBATCH, HID, HID, 0);
        tgemm<<<dim3(G3 / 128, 1), 256, SMG>>>(msgp, nullptr,
                                               Wx_c + (size_t)l * HID * G3,
                                               bx_c + (size_t)l * G3, nullptr,
                                               msgrow, NBATCH, HID, G3, 0);
        float* outp = (l == LLAYER - 1) ? (float*)d_out : ENC;
        GruArgs ac{XW1, Wh_c + (size_t)l * HID * G3, bh_c + (size_t)l * G3,
                   outp, hA0, hA1, flags + (2 + l) * 64 * FSTR, 0};
        ProdArgs pc{ENC, Wcomb + (size_t)l * HID * G3, msgrow, XW1,
                    chunks + l * 256, 84};
        gru_fused<<<148, 256, S_TOTAL>>>(ac, pc);
    }

    // 5) tail output + flag reset for graph replay
    lasth_kernel<<<(BBATCH * HID + 255) / 256, 256>>>(
        (const float*)d_out, (float*)d_out + (size_t)TT * NBATCH * HID);
    reset_flags_kernel<<<32, 256>>>();
}